// round 2
// baseline (speedup 1.0000x reference)
#include <cuda_runtime.h>
#include <cuda_bf16.h>
#include <cstdint>

// Problem constants
#define MAXN 50000
#define D1   256   // D_IN and also H1*C1
#define H1   4
#define C1   64
#define C2   32

// ---------------- scratch (device globals; no allocation allowed) ------------
__device__ float g_h1 [MAXN * D1];     // layer-1 features (then ELU activations)
__device__ float g_out1[MAXN * D1];    // layer-1 unnormalized aggregation
__device__ float g_as1[MAXN * H1];
__device__ float g_ad1[MAXN * H1];
__device__ float g_den1[MAXN * H1];
__device__ float g_h2 [MAXN * C2];
__device__ float g_as2[MAXN];
__device__ float g_ad2[MAXN];
__device__ float g_den2[MAXN];

// ---------------- zero scratch + output -------------------------------------
__global__ void zero_scratch(float* __restrict__ dout, int Nn) {
    long long total = (long long)Nn * D1 + (long long)Nn * H1 + Nn + (long long)Nn * C2;
    long long stride = (long long)gridDim.x * blockDim.x;
    for (long long i = (long long)blockIdx.x * blockDim.x + threadIdx.x; i < total; i += stride) {
        long long j = i;
        if (j < (long long)Nn * D1) { g_out1[j] = 0.f; continue; }
        j -= (long long)Nn * D1;
        if (j < (long long)Nn * H1) { g_den1[j] = 0.f; continue; }
        j -= (long long)Nn * H1;
        if (j < Nn) { g_den2[j] = 0.f; continue; }
        j -= Nn;
        dout[j] = 0.f;
    }
}

// ---------------- tiled fp32 SGEMM ------------------------------------------
template<int BM, int BN, int BK, int TM, int TN>
__global__ void sgemm(const float* __restrict__ A, const float* __restrict__ B,
                      float* __restrict__ C, int M, int N, int K) {
    __shared__ float As[BK][BM];
    __shared__ float Bs[BK][BN];
    constexpr int THREADS = (BM / TM) * (BN / TN);
    const int tid = threadIdx.x;
    const int tx  = tid % (BN / TN);
    const int ty  = tid / (BN / TN);
    const int row0 = blockIdx.y * BM;
    const int col0 = blockIdx.x * BN;

    float acc[TM][TN];
#pragma unroll
    for (int i = 0; i < TM; i++)
#pragma unroll
        for (int j = 0; j < TN; j++) acc[i][j] = 0.f;

    for (int k0 = 0; k0 < K; k0 += BK) {
        for (int i = tid; i < BM * BK; i += THREADS) {
            int m = i / BK, k = i % BK;
            int gm = row0 + m;
            As[k][m] = (gm < M) ? A[(size_t)gm * K + k0 + k] : 0.f;
        }
        for (int i = tid; i < BK * BN; i += THREADS) {
            int k = i / BN, n = i % BN;
            int gn = col0 + n;
            Bs[k][n] = (gn < N) ? B[(size_t)(k0 + k) * N + gn] : 0.f;
        }
        __syncthreads();
#pragma unroll
        for (int k = 0; k < BK; k++) {
            float a[TM], b[TN];
#pragma unroll
            for (int i = 0; i < TM; i++) a[i] = As[k][ty * TM + i];
#pragma unroll
            for (int j = 0; j < TN; j++) b[j] = Bs[k][tx * TN + j];
#pragma unroll
            for (int i = 0; i < TM; i++)
#pragma unroll
                for (int j = 0; j < TN; j++) acc[i][j] += a[i] * b[j];
        }
        __syncthreads();
    }
#pragma unroll
    for (int i = 0; i < TM; i++) {
        int gm = row0 + ty * TM + i;
        if (gm >= M) continue;
#pragma unroll
        for (int j = 0; j < TN; j++) {
            int gn = col0 + tx * TN + j;
            if (gn < N) C[(size_t)gm * N + gn] = acc[i][j];
        }
    }
}

// ---------------- layer-1 attention coefficients (warp per node-head) -------
__global__ void att1_kernel(const float* __restrict__ asrc, const float* __restrict__ adst, int Nn) {
    int warp = (blockIdx.x * blockDim.x + threadIdx.x) >> 5;
    int lane = threadIdx.x & 31;
    if (warp >= Nn * H1) return;
    int n = warp >> 2, h = warp & 3;
    const float* row = g_h1 + (size_t)n * D1 + h * C1;
    float s = 0.f, d = 0.f;
#pragma unroll
    for (int i = 0; i < C1 / 32; i++) {
        int c = lane + 32 * i;
        float v = row[c];
        s += v * asrc[h * C1 + c];
        d += v * adst[h * C1 + c];
    }
#pragma unroll
    for (int off = 16; off; off >>= 1) {
        s += __shfl_down_sync(0xffffffffu, s, off);
        d += __shfl_down_sync(0xffffffffu, d, off);
    }
    if (lane == 0) { g_as1[warp] = s; g_ad1[warp] = d; }
}

// ---------------- layer-1 edge pass (warp per edge, incl. self-loops) -------
__global__ void edge1_kernel(const int* __restrict__ ei, int E, int Nn) {
    int warp = (blockIdx.x * blockDim.x + threadIdx.x) >> 5;
    int lane = threadIdx.x & 31;
    int Etot = E + Nn;
    if (warp >= Etot) return;
    int src, dst;
    if (warp < E) { src = ei[warp]; dst = ei[E + warp]; }
    else          { src = dst = warp - E; }

    float p = 0.f;
    if (lane < H1) {
        float e = g_as1[src * H1 + lane] + g_ad1[dst * H1 + lane];
        e = (e >= 0.f) ? e : 0.2f * e;
        p = __expf(e);
        atomicAdd(&g_den1[dst * H1 + lane], p);
    }
    float p0 = __shfl_sync(0xffffffffu, p, 0);
    float p1 = __shfl_sync(0xffffffffu, p, 1);
    float p2 = __shfl_sync(0xffffffffu, p, 2);
    float p3 = __shfl_sync(0xffffffffu, p, 3);

    const float* hs = g_h1 + (size_t)src * D1;
    float*       od = g_out1 + (size_t)dst * D1;
#pragma unroll
    for (int i = 0; i < D1 / 32; i++) {
        int j = lane + 32 * i;
        float ph = (i < 2) ? p0 : (i < 4) ? p1 : (i < 6) ? p2 : p3;
        atomicAdd(&od[j], ph * __ldg(&hs[j]));
    }
}

// ---------------- layer-1 finalize: normalize + bias + ELU -> g_h1 ----------
__global__ void fin1_kernel(const float* __restrict__ b1, int Nn) {
    long long idx = (long long)blockIdx.x * blockDim.x + threadIdx.x;
    if (idx >= (long long)Nn * D1) return;
    int n = (int)(idx >> 8);
    int h = (int)((idx >> 6) & 3);
    float v = g_out1[idx] / g_den1[n * H1 + h] + b1[idx & (D1 - 1)];
    g_h1[idx] = (v > 0.f) ? v : (__expf(v) - 1.f);
}

// ---------------- layer-2 attention coefficients (warp per node) ------------
__global__ void att2_kernel(const float* __restrict__ asrc, const float* __restrict__ adst, int Nn) {
    int warp = (blockIdx.x * blockDim.x + threadIdx.x) >> 5;
    int lane = threadIdx.x & 31;
    if (warp >= Nn) return;
    float v = g_h2[(size_t)warp * C2 + lane];
    float s = v * asrc[lane];
    float d = v * adst[lane];
#pragma unroll
    for (int off = 16; off; off >>= 1) {
        s += __shfl_down_sync(0xffffffffu, s, off);
        d += __shfl_down_sync(0xffffffffu, d, off);
    }
    if (lane == 0) { g_as2[warp] = s; g_ad2[warp] = d; }
}

// ---------------- layer-2 edge pass (warp per edge) --------------------------
__global__ void edge2_kernel(const int* __restrict__ ei, int E, int Nn, float* __restrict__ out) {
    int warp = (blockIdx.x * blockDim.x + threadIdx.x) >> 5;
    int lane = threadIdx.x & 31;
    int Etot = E + Nn;
    if (warp >= Etot) return;
    int src, dst;
    if (warp < E) { src = ei[warp]; dst = ei[E + warp]; }
    else          { src = dst = warp - E; }

    float e = g_as2[src] + g_ad2[dst];
    e = (e >= 0.f) ? e : 0.2f * e;
    float p = __expf(e);
    if (lane == 0) atomicAdd(&g_den2[dst], p);
    atomicAdd(&out[(size_t)dst * C2 + lane], p * __ldg(&g_h2[(size_t)src * C2 + lane]));
}

// ---------------- layer-2 finalize ------------------------------------------
__global__ void fin2_kernel(float* __restrict__ out, const float* __restrict__ b2, int Nn) {
    int idx = blockIdx.x * blockDim.x + threadIdx.x;
    if (idx >= Nn * C2) return;
    out[idx] = out[idx] / g_den2[idx >> 5] + b2[idx & (C2 - 1)];
}

// ---------------- host orchestration ----------------------------------------
extern "C" void kernel_launch(void* const* d_in, const int* in_sizes, int n_in,
                              void* d_out, int out_size) {
    const float* x      = (const float*)d_in[0];
    const int*   ei     = (const int*)  d_in[1];
    const float* W1     = (const float*)d_in[2];
    const float* asrc1  = (const float*)d_in[3];
    const float* adst1  = (const float*)d_in[4];
    const float* b1     = (const float*)d_in[5];
    const float* W2     = (const float*)d_in[6];
    const float* asrc2  = (const float*)d_in[7];
    const float* adst2  = (const float*)d_in[8];
    const float* b2     = (const float*)d_in[9];
    float* out = (float*)d_out;

    const int Nn = in_sizes[0] / D1;     // 50000
    const int E  = in_sizes[1] / 2;      // 800000
    const int Etot = E + Nn;

    // Resolve DEVICE addresses of __device__ scratch for host-side kernel args.
    // (Passing the symbol directly from host silently yields the host shadow
    //  address, which GB300's ATS makes a *valid* GPU pointer -> silent wrong answer.)
    float *p_h1 = nullptr, *p_h2 = nullptr;
    cudaGetSymbolAddress((void**)&p_h1, g_h1);
    cudaGetSymbolAddress((void**)&p_h2, g_h2);

    // 0) zero accumulators + output
    zero_scratch<<<4096, 256>>>(out, Nn);

    // 1) GEMM1: g_h1 = x @ W1   [Nn,256] x [256,256]
    {
        dim3 grid(D1 / 64, (Nn + 63) / 64);
        sgemm<64, 64, 16, 4, 4><<<grid, 256>>>(x, W1, p_h1, Nn, D1, D1);
    }

    // 2) layer-1 attention coefficients
    att1_kernel<<<(Nn * H1 + 7) / 8, 256>>>(asrc1, adst1, Nn);

    // 3) layer-1 edge softmax + aggregation (single pass, normalization deferred)
    edge1_kernel<<<(Etot + 7) / 8, 256>>>(ei, E, Nn);

    // 4) finalize layer 1 -> ELU activations in g_h1
    fin1_kernel<<<(Nn * D1 + 255) / 256, 256>>>(b1, Nn);

    // 5) GEMM2: g_h2 = act @ W2   [Nn,256] x [256,32]
    {
        dim3 grid(1, (Nn + 63) / 64);
        sgemm<64, 32, 16, 4, 4><<<grid, 128>>>(p_h1, W2, p_h2, Nn, C2, D1);
    }

    // 6) layer-2 attention coefficients
    att2_kernel<<<(Nn + 7) / 8, 256>>>(asrc2, adst2, Nn);

    // 7) layer-2 edge pass (accumulates straight into d_out)
    edge2_kernel<<<(Etot + 7) / 8, 256>>>(ei, E, Nn, out);

    // 8) finalize layer 2
    fin2_kernel<<<(Nn * C2 + 255) / 256, 256>>>(out, b2, Nn);
}

// round 4
// speedup vs baseline: 1.2805x; 1.2805x over previous
#include <cuda_runtime.h>
#include <cuda_bf16.h>
#include <cstdint>

#define MAXN 50000
#define D1   256
#define H1   4
#define C2   32
#define KEXT 768

// ---------------- scratch (device globals) -----------------------------------
__device__ float g_h1 [MAXN * D1];
__device__ float g_out1[MAXN * D1];
__device__ float g_as1[MAXN * H1];
__device__ float g_ad1[MAXN * H1];
__device__ float g_den1[MAXN * H1];
__device__ float g_h2 [MAXN * C2];
__device__ float g_as2[MAXN];
__device__ float g_ad2[MAXN];
__device__ float g_den2[MAXN];
__device__ __nv_bfloat16 g_aext [MAXN * KEXT];     // A ext: [hi | hi | lo]
__device__ __nv_bfloat16 g_wext1[D1 * KEXT];       // W1^T ext: [hi | lo | hi]
__device__ __nv_bfloat16 g_wext2[C2 * KEXT];       // W2^T ext

// ---------------- helpers -----------------------------------------------------
__device__ __forceinline__ uint32_t smem_u32(const void* p) {
    uint32_t a;
    asm("{ .reg .u64 t; cvta.to.shared.u64 t, %1; cvt.u32.u64 %0, t; }" : "=r"(a) : "l"(p));
    return a;
}
__device__ __forceinline__ void cp_async16(uint32_t saddr, const void* gptr) {
    asm volatile("cp.async.cg.shared.global [%0], [%1], 16;"
        :: "r"(saddr), "l"(__cvta_generic_to_global(gptr)) : "memory");
}
#define CP_COMMIT asm volatile("cp.async.commit_group;" ::: "memory")
#define CP_WAIT0  asm volatile("cp.async.wait_group 0;" ::: "memory")

__device__ __forceinline__ void mma16816(float* c, const uint32_t* a, uint32_t b0, uint32_t b1) {
    asm volatile("mma.sync.aligned.m16n8k16.row.col.f32.bf16.bf16.f32 "
        "{%0,%1,%2,%3}, {%4,%5,%6,%7}, {%8,%9}, {%0,%1,%2,%3};"
        : "+f"(c[0]), "+f"(c[1]), "+f"(c[2]), "+f"(c[3])
        : "r"(a[0]), "r"(a[1]), "r"(a[2]), "r"(a[3]), "r"(b0), "r"(b1));
}
__device__ __forceinline__ void red_add_v4(float* gptr, float4 v) {
    asm volatile("red.global.add.v4.f32 [%0], {%1,%2,%3,%4};"
        :: "l"(__cvta_generic_to_global(gptr)), "f"(v.x), "f"(v.y), "f"(v.z), "f"(v.w) : "memory");
}

// ---------------- zero scratch + output --------------------------------------
__global__ void zero_scratch(float* __restrict__ dout, int Nn) {
    long long total = (long long)Nn * D1 + (long long)Nn * H1 + Nn + (long long)Nn * C2;
    long long stride = (long long)gridDim.x * blockDim.x;
    for (long long i = (long long)blockIdx.x * blockDim.x + threadIdx.x; i < total; i += stride) {
        long long j = i;
        if (j < (long long)Nn * D1) { g_out1[j] = 0.f; continue; }
        j -= (long long)Nn * D1;
        if (j < (long long)Nn * H1) { g_den1[j] = 0.f; continue; }
        j -= (long long)Nn * H1;
        if (j < Nn) { g_den2[j] = 0.f; continue; }
        j -= Nn;
        dout[j] = 0.f;
    }
}

// ---------------- weight ext prep ---------------------------------------------
__global__ void prep_w(const float* __restrict__ W1, const float* __restrict__ W2) {
    int idx = blockIdx.x * blockDim.x + threadIdx.x;
    if (idx < D1 * D1) {
        int k = idx >> 8, n = idx & 255;
        float w = W1[k * D1 + n];
        __nv_bfloat16 h = __float2bfloat16_rn(w);
        __nv_bfloat16 l = __float2bfloat16_rn(w - __bfloat162float(h));
        g_wext1[(size_t)n * KEXT + k]       = h;
        g_wext1[(size_t)n * KEXT + 256 + k] = l;
        g_wext1[(size_t)n * KEXT + 512 + k] = h;
    } else if (idx < D1 * D1 + D1 * C2) {
        int j = idx - D1 * D1;
        int k = j >> 5, n = j & 31;
        float w = W2[k * C2 + n];
        __nv_bfloat16 h = __float2bfloat16_rn(w);
        __nv_bfloat16 l = __float2bfloat16_rn(w - __bfloat162float(h));
        g_wext2[(size_t)n * KEXT + k]       = h;
        g_wext2[(size_t)n * KEXT + 256 + k] = l;
        g_wext2[(size_t)n * KEXT + 512 + k] = h;
    }
}

// ---------------- A ext prep: x -> [hi|hi|lo] ---------------------------------
__global__ void prep_a1(const float* __restrict__ x, int Nn) {
    int idx = blockIdx.x * blockDim.x + threadIdx.x;
    if (idx >= Nn * D1) return;
    int row = idx >> 8, k = idx & 255;
    float v = x[idx];
    __nv_bfloat16 h = __float2bfloat16_rn(v);
    __nv_bfloat16 l = __float2bfloat16_rn(v - __bfloat162float(h));
    size_t base = (size_t)row * KEXT;
    g_aext[base + k]       = h;
    g_aext[base + 256 + k] = h;
    g_aext[base + 512 + k] = l;
}

// ---------------- fin1 fused into A ext prep for layer 2 ----------------------
__global__ void fin1ext(const float* __restrict__ b1, int Nn) {
    int idx = blockIdx.x * blockDim.x + threadIdx.x;
    if (idx >= Nn * D1) return;
    int row = idx >> 8, k = idx & 255;
    float v = g_out1[idx] / g_den1[(row << 2) | (k >> 6)] + b1[k];
    v = (v > 0.f) ? v : (__expf(v) - 1.f);
    __nv_bfloat16 h = __float2bfloat16_rn(v);
    __nv_bfloat16 l = __float2bfloat16_rn(v - __bfloat162float(h));
    size_t base = (size_t)row * KEXT;
    g_aext[base + k]       = h;
    g_aext[base + 256 + k] = h;
    g_aext[base + 512 + k] = l;
}

// ---------------- HMMA GEMM (double-buffered cp.async) ------------------------
// C[M, NTOT] = Aext[M,768] x Bext[NTOT,768]^T, fused att epilogue.
template<int BN>
__global__ void __launch_bounds__(256)
gemm_mma(const __nv_bfloat16* __restrict__ Aext,
         const __nv_bfloat16* __restrict__ Bext,
         float* __restrict__ Cout,
         const float* __restrict__ att_s, const float* __restrict__ att_d,
         float* __restrict__ out_s, float* __restrict__ out_d, int M)
{
    constexpr int BM = 128, BK = 64, KT = KEXT / BK;   // 12 k-tiles
    constexpr int LDA = 72;                            // bf16 elems per smem row
    constexpr int WN = (BN == 128) ? 64 : 32;
    constexpr int WX = BN / WN, WY = 8 / WX;
    constexpr int MROWS = BM / WY, MT_ = MROWS / 16, NT_ = WN / 8;
    constexpr int NTOT = BN * ((BN == 128) ? 2 : 1);   // 256 or 32
    constexpr int HEADC = WN, NH = NTOT / HEADC;
    constexpr int ABYTES = BM * LDA * 2;
    constexpr int BBYTES = BN * LDA * 2;

    extern __shared__ char sm[];
    char* smA = sm;
    char* smB = sm + 2 * ABYTES;
    float* s_as = (float*)(sm + 2 * ABYTES + 2 * BBYTES);
    float* s_ad = s_as + NTOT;

    const int tid = threadIdx.x;
    const int lane = tid & 31, wid = tid >> 5;
    const int wx = wid % WX, wy = wid / WX;
    const int bx = blockIdx.x;
    const int m0 = blockIdx.y * BM;
    const int n0 = bx * BN;

    if (tid < NTOT) { s_as[tid] = att_s[tid]; s_ad[tid] = att_d[tid]; }

    const uint32_t aBase = smem_u32(smA);
    const uint32_t bBase = smem_u32(smB);

    auto issue = [&](int kt, int buf) {
#pragma unroll
        for (int i = 0; i < (BM * BK / 8) / 256; i++) {     // A: 1024 chunks
            int idx = tid + i * 256;
            int r = idx >> 3, c4 = idx & 7;
            int row = m0 + r; if (row > M - 1) row = M - 1;
            cp_async16(aBase + buf * ABYTES + (r * LDA + c4 * 8) * 2,
                       Aext + (size_t)row * KEXT + kt * BK + c4 * 8);
        }
#pragma unroll
        for (int i = 0; i < (BN * BK / 8) / 256; i++) {     // B: 1024 or 256 chunks
            int idx = tid + i * 256;
            int r = idx >> 3, c4 = idx & 7;
            cp_async16(bBase + buf * BBYTES + (r * LDA + c4 * 8) * 2,
                       Bext + (size_t)(n0 + r) * KEXT + kt * BK + c4 * 8);
        }
        CP_COMMIT;
    };

    float acc[MT_][NT_][4];
#pragma unroll
    for (int mt = 0; mt < MT_; mt++)
#pragma unroll
        for (int nt = 0; nt < NT_; nt++)
#pragma unroll
            for (int q = 0; q < 4; q++) acc[mt][nt][q] = 0.f;

    issue(0, 0);
    for (int kt = 0; kt < KT; kt++) {
        CP_WAIT0;
        __syncthreads();
        if (kt + 1 < KT) issue(kt + 1, (kt + 1) & 1);
        const char* Ab = smA + (kt & 1) * ABYTES;
        const char* Bb = smB + (kt & 1) * BBYTES;
#pragma unroll
        for (int ks = 0; ks < 4; ks++) {
            const int kq = ks * 16 + (lane & 3) * 2;
            uint32_t a[MT_][4];
#pragma unroll
            for (int mt = 0; mt < MT_; mt++) {
                int row = wy * MROWS + mt * 16 + (lane >> 2);
                const char* ap = Ab + (row * LDA + kq) * 2;
                a[mt][0] = *(const uint32_t*)ap;
                a[mt][2] = *(const uint32_t*)(ap + 16);
                a[mt][1] = *(const uint32_t*)(ap + 8 * LDA * 2);
                a[mt][3] = *(const uint32_t*)(ap + 8 * LDA * 2 + 16);
            }
#pragma unroll
            for (int nt = 0; nt < NT_; nt++) {
                int n = wx * WN + nt * 8 + (lane >> 2);
                const char* bp = Bb + (n * LDA + kq) * 2;
                uint32_t b0 = *(const uint32_t*)bp;
                uint32_t b1 = *(const uint32_t*)(bp + 16);
#pragma unroll
                for (int mt = 0; mt < MT_; mt++)
                    mma16816(acc[mt][nt], a[mt], b0, b1);
            }
        }
        __syncthreads();
    }

    // epilogue: store C + fused att dot products (warp covers exactly one head)
#pragma unroll
    for (int mt = 0; mt < MT_; mt++) {
        int row = m0 + wy * MROWS + mt * 16 + (lane >> 2);
        float s0 = 0.f, d0 = 0.f, s1 = 0.f, d1 = 0.f;
#pragma unroll
        for (int nt = 0; nt < NT_; nt++) {
            int col = n0 + wx * WN + nt * 8 + (lane & 3) * 2;
            float c0 = acc[mt][nt][0], c1 = acc[mt][nt][1];
            float c2 = acc[mt][nt][2], c3 = acc[mt][nt][3];
            if (row < M)     *(float2*)&Cout[(size_t)row * NTOT + col]       = make_float2(c0, c1);
            if (row + 8 < M) *(float2*)&Cout[(size_t)(row + 8) * NTOT + col] = make_float2(c2, c3);
            s0 += c0 * s_as[col] + c1 * s_as[col + 1];
            d0 += c0 * s_ad[col] + c1 * s_ad[col + 1];
            s1 += c2 * s_as[col] + c3 * s_as[col + 1];
            d1 += c2 * s_ad[col] + c3 * s_ad[col + 1];
        }
#pragma unroll
        for (int off = 1; off <= 2; off <<= 1) {
            s0 += __shfl_xor_sync(0xffffffffu, s0, off);
            d0 += __shfl_xor_sync(0xffffffffu, d0, off);
            s1 += __shfl_xor_sync(0xffffffffu, s1, off);
            d1 += __shfl_xor_sync(0xffffffffu, d1, off);
        }
        if ((lane & 3) == 0) {
            int head = (n0 + wx * WN) / HEADC;
            if (row < M)     { out_s[row * NH + head] = s0;       out_d[row * NH + head] = d0; }
            if (row + 8 < M) { out_s[(row + 8) * NH + head] = s1; out_d[(row + 8) * NH + head] = d1; }
        }
    }
}

// ---------------- layer-1 edge pass (warp/edge, v4 red atomics) ---------------
__global__ void edge1_kernel(const int* __restrict__ ei, int E, int Nn) {
    int warp = (blockIdx.x * blockDim.x + threadIdx.x) >> 5;
    int lane = threadIdx.x & 31;
    int Etot = E + Nn;
    if (warp >= Etot) return;
    int src, dst;
    if (warp < E) { src = ei[warp]; dst = ei[E + warp]; }
    else          { src = dst = warp - E; }

    float p = 0.f;
    if (lane < H1) {
        float e = g_as1[src * H1 + lane] + g_ad1[dst * H1 + lane];
        e = (e >= 0.f) ? e : 0.2f * e;
        p = __expf(e);
        atomicAdd(&g_den1[dst * H1 + lane], p);
    }
    const float4* hs4 = (const float4*)(g_h1 + (size_t)src * D1);
    float4*       od4 = (float4*)(g_out1 + (size_t)dst * D1);
#pragma unroll
    for (int it = 0; it < 2; it++) {
        int j = lane + 32 * it;                    // float4 index 0..63
        float ph = __shfl_sync(0xffffffffu, p, j >> 4);
        float4 hv = __ldg(hs4 + j);
        red_add_v4(&od4[j].x, make_float4(ph * hv.x, ph * hv.y, ph * hv.z, ph * hv.w));
    }
}

// ---------------- layer-2 edge pass (4 edges/warp, v4 red) --------------------
__global__ void edge2_kernel(const int* __restrict__ ei, int E, int Nn, float* __restrict__ out) {
    int warp = (blockIdx.x * blockDim.x + threadIdx.x) >> 5;
    int lane = threadIdx.x & 31;
    int gid = warp * 4 + (lane >> 3);
    int lq = lane & 7;
    int Etot = E + Nn;
    if (gid >= Etot) return;
    int src, dst;
    if (gid < E) { src = ei[gid]; dst = ei[E + gid]; }
    else         { src = dst = gid - E; }

    float e = g_as2[src] + g_ad2[dst];
    e = (e >= 0.f) ? e : 0.2f * e;
    float p = __expf(e);
    if (lq == 0) atomicAdd(&g_den2[dst], p);
    float4 hv = __ldg((const float4*)(g_h2 + (size_t)src * C2) + lq);
    red_add_v4(out + (size_t)dst * C2 + lq * 4,
               make_float4(p * hv.x, p * hv.y, p * hv.z, p * hv.w));
}

// ---------------- layer-2 finalize --------------------------------------------
__global__ void fin2_kernel(float* __restrict__ out, const float* __restrict__ b2, int Nn) {
    int idx = blockIdx.x * blockDim.x + threadIdx.x;
    if (idx >= Nn * C2) return;
    out[idx] = out[idx] / g_den2[idx >> 5] + b2[idx & (C2 - 1)];
}

// ---------------- host orchestration ------------------------------------------
extern "C" void kernel_launch(void* const* d_in, const int* in_sizes, int n_in,
                              void* d_out, int out_size) {
    const float* x     = (const float*)d_in[0];
    const int*   ei    = (const int*)  d_in[1];
    const float* W1    = (const float*)d_in[2];
    const float* asrc1 = (const float*)d_in[3];
    const float* adst1 = (const float*)d_in[4];
    const float* b1    = (const float*)d_in[5];
    const float* W2    = (const float*)d_in[6];
    const float* asrc2 = (const float*)d_in[7];
    const float* adst2 = (const float*)d_in[8];
    const float* b2    = (const float*)d_in[9];
    float* out = (float*)d_out;

    const int Nn = in_sizes[0] / D1;
    const int E  = in_sizes[1] / 2;
    const int Etot = E + Nn;
    const int MT = (Nn + 127) / 128;

    // resolve device addresses of __device__ globals (host symbol != device addr!)
    __nv_bfloat16 *p_aext, *p_w1, *p_w2;
    float *p_h1, *p_h2, *p_as1, *p_ad1, *p_as2, *p_ad2;
    cudaGetSymbolAddress((void**)&p_aext, g_aext);
    cudaGetSymbolAddress((void**)&p_w1,   g_wext1);
    cudaGetSymbolAddress((void**)&p_w2,   g_wext2);
    cudaGetSymbolAddress((void**)&p_h1,   g_h1);
    cudaGetSymbolAddress((void**)&p_h2,   g_h2);
    cudaGetSymbolAddress((void**)&p_as1,  g_as1);
    cudaGetSymbolAddress((void**)&p_ad1,  g_ad1);
    cudaGetSymbolAddress((void**)&p_as2,  g_as2);
    cudaGetSymbolAddress((void**)&p_ad2,  g_ad2);

    constexpr int SM1 = 2 * 128 * 72 * 2 + 2 * 128 * 72 * 2 + 2 * 256 * 4;  // 75776
    constexpr int SM2 = 2 * 128 * 72 * 2 + 2 * 32 * 72 * 2 + 2 * 32 * 4;    // 46336
    cudaFuncSetAttribute(gemm_mma<128>, cudaFuncAttributeMaxDynamicSharedMemorySize, SM1);
    cudaFuncSetAttribute(gemm_mma<32>,  cudaFuncAttributeMaxDynamicSharedMemorySize, SM2);

    zero_scratch<<<4096, 256>>>(out, Nn);
    prep_w<<<(D1 * D1 + D1 * C2 + 255) / 256, 256>>>(W1, W2);
    prep_a1<<<(Nn * D1 + 255) / 256, 256>>>(x, Nn);
    gemm_mma<128><<<dim3(2, MT), 256, SM1>>>(p_aext, p_w1, p_h1, asrc1, adst1, p_as1, p_ad1, Nn);
    edge1_kernel<<<(Etot + 7) / 8, 256>>>(ei, E, Nn);
    fin1ext<<<(Nn * D1 + 255) / 256, 256>>>(b1, Nn);
    gemm_mma<32><<<dim3(1, MT), 256, SM2>>>(p_aext, p_w2, p_h2, asrc2, adst2, p_as2, p_ad2, Nn);
    edge2_kernel<<<(Etot + 31) / 32, 256>>>(ei, E, Nn, out);
    fin2_kernel<<<(Nn * C2 + 255) / 256, 256>>>(out, b2, Nn);
}

// round 5
// speedup vs baseline: 2.0824x; 1.6262x over previous
#include <cuda_runtime.h>
#include <cuda_bf16.h>
#include <cstdint>

#define MAXN 50000
#define MAXE 900080        // capacity for E + N self-loops
#define D1   256
#define H1   4
#define C2   32
#define KEXT 768

// ---------------- scratch (device globals) -----------------------------------
__device__ float g_h1 [MAXN * D1];
__device__ float g_as1[MAXN * H1];
__device__ float g_ad1[MAXN * H1];
__device__ float g_h2 [MAXN * C2];
__device__ float g_as2[MAXN];
__device__ float g_ad2[MAXN];
__device__ __nv_bfloat16 g_aext [MAXN * KEXT];     // A ext: [hi | hi | lo]
__device__ __nv_bfloat16 g_wext1[D1 * KEXT];       // W1^T ext: [hi | lo | hi]
__device__ __nv_bfloat16 g_wext2[C2 * KEXT];
__device__ int g_row[MAXN + 1];                    // CSR row offsets (by dst)
__device__ int g_cur[MAXN];                        // counts, then write cursors
__device__ int g_csr[MAXE];                        // src ids grouped by dst

// ---------------- helpers -----------------------------------------------------
__device__ __forceinline__ uint32_t smem_u32(const void* p) {
    uint32_t a;
    asm("{ .reg .u64 t; cvta.to.shared.u64 t, %1; cvt.u32.u64 %0, t; }" : "=r"(a) : "l"(p));
    return a;
}
__device__ __forceinline__ void cp_async16(uint32_t saddr, const void* gptr) {
    asm volatile("cp.async.cg.shared.global [%0], [%1], 16;"
        :: "r"(saddr), "l"(__cvta_generic_to_global(gptr)) : "memory");
}
#define CP_COMMIT asm volatile("cp.async.commit_group;" ::: "memory")
#define CP_WAIT0  asm volatile("cp.async.wait_group 0;" ::: "memory")

__device__ __forceinline__ void mma16816(float* c, const uint32_t* a, uint32_t b0, uint32_t b1) {
    asm volatile("mma.sync.aligned.m16n8k16.row.col.f32.bf16.bf16.f32 "
        "{%0,%1,%2,%3}, {%4,%5,%6,%7}, {%8,%9}, {%0,%1,%2,%3};"
        : "+f"(c[0]), "+f"(c[1]), "+f"(c[2]), "+f"(c[3])
        : "r"(a[0]), "r"(a[1]), "r"(a[2]), "r"(a[3]), "r"(b0), "r"(b1));
}
__device__ __forceinline__ uint32_t pack_bf16x2(float a, float b) {
    __nv_bfloat16 ha = __float2bfloat16_rn(a), hb = __float2bfloat16_rn(b);
    return (uint32_t)__bfloat16_as_ushort(ha) | ((uint32_t)__bfloat16_as_ushort(hb) << 16);
}

// ---------------- weight ext prep ---------------------------------------------
__global__ void prep_w(const float* __restrict__ W1, const float* __restrict__ W2) {
    int idx = blockIdx.x * blockDim.x + threadIdx.x;
    if (idx < D1 * D1) {
        int k = idx >> 8, n = idx & 255;
        float w = W1[k * D1 + n];
        __nv_bfloat16 h = __float2bfloat16_rn(w);
        __nv_bfloat16 l = __float2bfloat16_rn(w - __bfloat162float(h));
        g_wext1[(size_t)n * KEXT + k]       = h;
        g_wext1[(size_t)n * KEXT + 256 + k] = l;
        g_wext1[(size_t)n * KEXT + 512 + k] = h;
    } else if (idx < D1 * D1 + D1 * C2) {
        int j = idx - D1 * D1;
        int k = j >> 5, n = j & 31;
        float w = W2[k * C2 + n];
        __nv_bfloat16 h = __float2bfloat16_rn(w);
        __nv_bfloat16 l = __float2bfloat16_rn(w - __bfloat162float(h));
        g_wext2[(size_t)n * KEXT + k]       = h;
        g_wext2[(size_t)n * KEXT + 256 + k] = l;
        g_wext2[(size_t)n * KEXT + 512 + k] = h;
    }
}

// ---------------- A ext prep: x -> [hi|hi|lo] ---------------------------------
__global__ void prep_a1(const float* __restrict__ x, int Nn) {
    int idx = blockIdx.x * blockDim.x + threadIdx.x;
    if (idx >= Nn * D1) return;
    int row = idx >> 8, k = idx & 255;
    float v = x[idx];
    __nv_bfloat16 h = __float2bfloat16_rn(v);
    __nv_bfloat16 l = __float2bfloat16_rn(v - __bfloat162float(h));
    size_t base = (size_t)row * KEXT;
    g_aext[base + k]       = h;
    g_aext[base + 256 + k] = h;
    g_aext[base + 512 + k] = l;
}

// ---------------- CSR build ----------------------------------------------------
__global__ void csr_init(int Nn) {
    int i = blockIdx.x * blockDim.x + threadIdx.x;
    if (i < Nn) g_cur[i] = 1;                          // self-loop per node
}
__global__ void csr_count(const int* __restrict__ ei, int E) {
    int i = blockIdx.x * blockDim.x + threadIdx.x;
    if (i < E) atomicAdd(&g_cur[ei[E + i]], 1);
}
__global__ void csr_scan(int Nn) {                     // single block, 1024 threads
    __shared__ int s[1024];
    const int t = threadIdx.x;
    const int chunk = (Nn + 1023) / 1024;
    const int beg = t * chunk;
    const int end = (beg + chunk < Nn) ? beg + chunk : Nn;
    int sum = 0;
    for (int i = beg; i < end; i++) sum += g_cur[i];
    s[t] = sum;
    __syncthreads();
    int run_in = sum;
    for (int d = 1; d < 1024; d <<= 1) {
        int v = (t >= d) ? s[t - d] : 0;
        __syncthreads();
        s[t] += v;
        __syncthreads();
    }
    int off = s[t] - run_in;                           // exclusive prefix
    int run = off;
    for (int i = beg; i < end; i++) {
        int c = g_cur[i];
        g_row[i] = run;
        g_cur[i] = run;
        run += c;
    }
    if (end == Nn && beg <= Nn) g_row[Nn] = run;
}
__global__ void csr_scatter(const int* __restrict__ ei, int E, int Nn) {
    int i = blockIdx.x * blockDim.x + threadIdx.x;
    int Etot = E + Nn;
    if (i >= Etot) return;
    int src, dst;
    if (i < E) { src = ei[i]; dst = ei[E + i]; }
    else       { src = dst = i - E; }
    int pos = atomicAdd(&g_cur[dst], 1);
    g_csr[pos] = src;
}

// ---------------- HMMA GEMM (double-buffered cp.async, fused att epilogue) ----
template<int BN>
__global__ void __launch_bounds__(256)
gemm_mma(const __nv_bfloat16* __restrict__ Aext,
         const __nv_bfloat16* __restrict__ Bext,
         float* __restrict__ Cout,
         const float* __restrict__ att_s, const float* __restrict__ att_d,
         float* __restrict__ out_s, float* __restrict__ out_d, int M)
{
    constexpr int BM = 128, BK = 64, KT = KEXT / BK;
    constexpr int LDA = 72;
    constexpr int WN = (BN == 128) ? 64 : 32;
    constexpr int WX = BN / WN, WY = 8 / WX;
    constexpr int MROWS = BM / WY, MT_ = MROWS / 16, NT_ = WN / 8;
    constexpr int NTOT = BN * ((BN == 128) ? 2 : 1);
    constexpr int HEADC = WN, NH = NTOT / HEADC;
    constexpr int ABYTES = BM * LDA * 2;
    constexpr int BBYTES = BN * LDA * 2;

    extern __shared__ char sm[];
    char* smA = sm;
    char* smB = sm + 2 * ABYTES;
    float* s_as = (float*)(sm + 2 * ABYTES + 2 * BBYTES);
    float* s_ad = s_as + NTOT;

    const int tid = threadIdx.x;
    const int lane = tid & 31, wid = tid >> 5;
    const int wx = wid % WX, wy = wid / WX;
    const int m0 = blockIdx.y * BM;
    const int n0 = blockIdx.x * BN;

    if (tid < NTOT) { s_as[tid] = att_s[tid]; s_ad[tid] = att_d[tid]; }

    const uint32_t aBase = smem_u32(smA);
    const uint32_t bBase = smem_u32(smB);

    auto issue = [&](int kt, int buf) {
#pragma unroll
        for (int i = 0; i < (BM * BK / 8) / 256; i++) {
            int idx = tid + i * 256;
            int r = idx >> 3, c4 = idx & 7;
            int row = m0 + r; if (row > M - 1) row = M - 1;
            cp_async16(aBase + buf * ABYTES + (r * LDA + c4 * 8) * 2,
                       Aext + (size_t)row * KEXT + kt * BK + c4 * 8);
        }
#pragma unroll
        for (int i = 0; i < (BN * BK / 8) / 256; i++) {
            int idx = tid + i * 256;
            int r = idx >> 3, c4 = idx & 7;
            cp_async16(bBase + buf * BBYTES + (r * LDA + c4 * 8) * 2,
                       Bext + (size_t)(n0 + r) * KEXT + kt * BK + c4 * 8);
        }
        CP_COMMIT;
    };

    float acc[MT_][NT_][4];
#pragma unroll
    for (int mt = 0; mt < MT_; mt++)
#pragma unroll
        for (int nt = 0; nt < NT_; nt++)
#pragma unroll
            for (int q = 0; q < 4; q++) acc[mt][nt][q] = 0.f;

    issue(0, 0);
    for (int kt = 0; kt < KT; kt++) {
        CP_WAIT0;
        __syncthreads();
        if (kt + 1 < KT) issue(kt + 1, (kt + 1) & 1);
        const char* Ab = smA + (kt & 1) * ABYTES;
        const char* Bb = smB + (kt & 1) * BBYTES;
#pragma unroll
        for (int ks = 0; ks < 4; ks++) {
            const int kq = ks * 16 + (lane & 3) * 2;
            uint32_t a[MT_][4];
#pragma unroll
            for (int mt = 0; mt < MT_; mt++) {
                int row = wy * MROWS + mt * 16 + (lane >> 2);
                const char* ap = Ab + (row * LDA + kq) * 2;
                a[mt][0] = *(const uint32_t*)ap;
                a[mt][2] = *(const uint32_t*)(ap + 16);
                a[mt][1] = *(const uint32_t*)(ap + 8 * LDA * 2);
                a[mt][3] = *(const uint32_t*)(ap + 8 * LDA * 2 + 16);
            }
#pragma unroll
            for (int nt = 0; nt < NT_; nt++) {
                int n = wx * WN + nt * 8 + (lane >> 2);
                const char* bp = Bb + (n * LDA + kq) * 2;
                uint32_t b0 = *(const uint32_t*)bp;
                uint32_t b1 = *(const uint32_t*)(bp + 16);
#pragma unroll
                for (int mt = 0; mt < MT_; mt++)
                    mma16816(acc[mt][nt], a[mt], b0, b1);
            }
        }
        __syncthreads();
    }

#pragma unroll
    for (int mt = 0; mt < MT_; mt++) {
        int row = m0 + wy * MROWS + mt * 16 + (lane >> 2);
        float s0 = 0.f, d0 = 0.f, s1 = 0.f, d1 = 0.f;
#pragma unroll
        for (int nt = 0; nt < NT_; nt++) {
            int col = n0 + wx * WN + nt * 8 + (lane & 3) * 2;
            float c0 = acc[mt][nt][0], c1 = acc[mt][nt][1];
            float c2 = acc[mt][nt][2], c3 = acc[mt][nt][3];
            if (row < M)     *(float2*)&Cout[(size_t)row * NTOT + col]       = make_float2(c0, c1);
            if (row + 8 < M) *(float2*)&Cout[(size_t)(row + 8) * NTOT + col] = make_float2(c2, c3);
            s0 += c0 * s_as[col] + c1 * s_as[col + 1];
            d0 += c0 * s_ad[col] + c1 * s_ad[col + 1];
            s1 += c2 * s_as[col] + c3 * s_as[col + 1];
            d1 += c2 * s_ad[col] + c3 * s_ad[col + 1];
        }
#pragma unroll
        for (int off = 1; off <= 2; off <<= 1) {
            s0 += __shfl_xor_sync(0xffffffffu, s0, off);
            d0 += __shfl_xor_sync(0xffffffffu, d0, off);
            s1 += __shfl_xor_sync(0xffffffffu, s1, off);
            d1 += __shfl_xor_sync(0xffffffffu, d1, off);
        }
        if ((lane & 3) == 0) {
            int head = (n0 + wx * WN) / HEADC;
            if (row < M)     { out_s[row * NH + head] = s0;       out_d[row * NH + head] = d0; }
            if (row + 8 < M) { out_s[(row + 8) * NH + head] = s1; out_d[(row + 8) * NH + head] = d1; }
        }
    }
}

// ---------------- layer-1 pull: warp per dst node ------------------------------
// acc = sum_src p * h1[src]; den = sum p. Epilogue fuses /den + b1 + ELU + bf16
// hi/lo ext emission for GEMM2.
__global__ void __launch_bounds__(256)
pull1(const float* __restrict__ b1, int Nn) {
    int warp = (blockIdx.x * blockDim.x + threadIdx.x) >> 5;
    int lane = threadIdx.x & 31;
    if (warp >= Nn) return;
    const int d = warp;
    const int base = g_row[d], end = g_row[d + 1];

    float adl = (lane < H1) ? g_ad1[d * H1 + lane] : 0.f;
    float4 acc1 = make_float4(0.f, 0.f, 0.f, 0.f);
    float4 acc2 = make_float4(0.f, 0.f, 0.f, 0.f);
    float den = 0.f;

    int src_next = g_csr[base];
    for (int i = base; i < end; i++) {
        int src = src_next;
        if (i + 1 < end) src_next = g_csr[i + 1];
        float p = 0.f;
        if (lane < H1) {
            float e = __ldg(&g_as1[src * H1 + lane]) + adl;
            e = (e >= 0.f) ? e : 0.2f * e;
            p = __expf(e);
            den += p;
        }
        float pa = __shfl_sync(0xffffffffu, p, lane >> 4);
        float pb = __shfl_sync(0xffffffffu, p, 2 + (lane >> 4));
        const float4* h4 = (const float4*)(g_h1 + (size_t)src * D1);
        float4 v1 = __ldg(h4 + lane);
        float4 v2 = __ldg(h4 + lane + 32);
        acc1.x += pa * v1.x; acc1.y += pa * v1.y; acc1.z += pa * v1.z; acc1.w += pa * v1.w;
        acc2.x += pb * v2.x; acc2.y += pb * v2.y; acc2.z += pb * v2.z; acc2.w += pb * v2.w;
    }

    float dena = __shfl_sync(0xffffffffu, den, lane >> 4);
    float denb = __shfl_sync(0xffffffffu, den, 2 + (lane >> 4));
    float inva = 1.f / dena, invb = 1.f / denb;

    size_t abase = (size_t)d * KEXT;
    int c1 = 4 * lane, c2 = 128 + 4 * lane;
    float v[8];
    v[0] = acc1.x * inva + __ldg(&b1[c1]);
    v[1] = acc1.y * inva + __ldg(&b1[c1 + 1]);
    v[2] = acc1.z * inva + __ldg(&b1[c1 + 2]);
    v[3] = acc1.w * inva + __ldg(&b1[c1 + 3]);
    v[4] = acc2.x * invb + __ldg(&b1[c2]);
    v[5] = acc2.y * invb + __ldg(&b1[c2 + 1]);
    v[6] = acc2.z * invb + __ldg(&b1[c2 + 2]);
    v[7] = acc2.w * invb + __ldg(&b1[c2 + 3]);
#pragma unroll
    for (int q = 0; q < 8; q++) v[q] = (v[q] > 0.f) ? v[q] : (__expf(v[q]) - 1.f);

#pragma unroll
    for (int g = 0; g < 2; g++) {
        int c = g ? c2 : c1;
        float a0 = v[4 * g], a1 = v[4 * g + 1], a2 = v[4 * g + 2], a3 = v[4 * g + 3];
        uint32_t h01 = pack_bf16x2(a0, a1);
        uint32_t h23 = pack_bf16x2(a2, a3);
        __nv_bfloat16 hb0 = __float2bfloat16_rn(a0), hb1 = __float2bfloat16_rn(a1);
        __nv_bfloat16 hb2 = __float2bfloat16_rn(a2), hb3 = __float2bfloat16_rn(a3);
        uint32_t l01 = pack_bf16x2(a0 - __bfloat162float(hb0), a1 - __bfloat162float(hb1));
        uint32_t l23 = pack_bf16x2(a2 - __bfloat162float(hb2), a3 - __bfloat162float(hb3));
        *(uint32_t*)&g_aext[abase + c]           = h01;
        *(uint32_t*)&g_aext[abase + c + 2]       = h23;
        *(uint32_t*)&g_aext[abase + 256 + c]     = h01;
        *(uint32_t*)&g_aext[abase + 256 + c + 2] = h23;
        *(uint32_t*)&g_aext[abase + 512 + c]     = l01;
        *(uint32_t*)&g_aext[abase + 512 + c + 2] = l23;
    }
}

// ---------------- layer-2 pull: warp per dst node, writes final output --------
__global__ void __launch_bounds__(256)
pull2(const float* __restrict__ b2, float* __restrict__ out, int Nn) {
    int warp = (blockIdx.x * blockDim.x + threadIdx.x) >> 5;
    int lane = threadIdx.x & 31;
    if (warp >= Nn) return;
    const int d = warp;
    const int base = g_row[d], end = g_row[d + 1];

    float ad = g_ad2[d];
    float acc = 0.f, den = 0.f;

    int src_next = g_csr[base];
    for (int i = base; i < end; i++) {
        int src = src_next;
        if (i + 1 < end) src_next = g_csr[i + 1];
        float p = 0.f;
        if (lane == 0) {
            float e = __ldg(&g_as2[src]) + ad;
            e = (e >= 0.f) ? e : 0.2f * e;
            p = __expf(e);
        }
        p = __shfl_sync(0xffffffffu, p, 0);
        den += p;
        acc += p * __ldg(&g_h2[(size_t)src * C2 + lane]);
    }
    out[(size_t)d * C2 + lane] = acc / den + __ldg(&b2[lane]);
}

// ---------------- host orchestration ------------------------------------------
extern "C" void kernel_launch(void* const* d_in, const int* in_sizes, int n_in,
                              void* d_out, int out_size) {
    const float* x     = (const float*)d_in[0];
    const int*   ei    = (const int*)  d_in[1];
    const float* W1    = (const float*)d_in[2];
    const float* asrc1 = (const float*)d_in[3];
    const float* adst1 = (const float*)d_in[4];
    const float* b1    = (const float*)d_in[5];
    const float* W2    = (const float*)d_in[6];
    const float* asrc2 = (const float*)d_in[7];
    const float* adst2 = (const float*)d_in[8];
    const float* b2    = (const float*)d_in[9];
    float* out = (float*)d_out;

    const int Nn = in_sizes[0] / D1;
    const int E  = in_sizes[1] / 2;
    const int Etot = E + Nn;
    const int MT = (Nn + 127) / 128;

    __nv_bfloat16 *p_aext, *p_w1, *p_w2;
    float *p_h1, *p_h2, *p_as1, *p_ad1, *p_as2, *p_ad2;
    cudaGetSymbolAddress((void**)&p_aext, g_aext);
    cudaGetSymbolAddress((void**)&p_w1,   g_wext1);
    cudaGetSymbolAddress((void**)&p_w2,   g_wext2);
    cudaGetSymbolAddress((void**)&p_h1,   g_h1);
    cudaGetSymbolAddress((void**)&p_h2,   g_h2);
    cudaGetSymbolAddress((void**)&p_as1,  g_as1);
    cudaGetSymbolAddress((void**)&p_ad1,  g_ad1);
    cudaGetSymbolAddress((void**)&p_as2,  g_as2);
    cudaGetSymbolAddress((void**)&p_ad2,  g_ad2);

    constexpr int SM1 = 2 * 128 * 72 * 2 + 2 * 128 * 72 * 2 + 2 * 256 * 4;
    constexpr int SM2 = 2 * 128 * 72 * 2 + 2 * 32 * 72 * 2 + 2 * 32 * 4;
    cudaFuncSetAttribute(gemm_mma<128>, cudaFuncAttributeMaxDynamicSharedMemorySize, SM1);
    cudaFuncSetAttribute(gemm_mma<32>,  cudaFuncAttributeMaxDynamicSharedMemorySize, SM2);

    // CSR build (independent of GEMM1 inputs)
    csr_init   <<<(Nn + 255) / 256, 256>>>(Nn);
    csr_count  <<<(E + 255) / 256, 256>>>(ei, E);
    csr_scan   <<<1, 1024>>>(Nn);
    csr_scatter<<<(Etot + 255) / 256, 256>>>(ei, E, Nn);

    prep_w <<<(D1 * D1 + D1 * C2 + 255) / 256, 256>>>(W1, W2);
    prep_a1<<<(Nn * D1 + 255) / 256, 256>>>(x, Nn);

    gemm_mma<128><<<dim3(2, MT), 256, SM1>>>(p_aext, p_w1, p_h1, asrc1, adst1, p_as1, p_ad1, Nn);
    pull1<<<(Nn + 7) / 8, 256>>>(b1, Nn);
    gemm_mma<32><<<dim3(1, MT), 256, SM2>>>(p_aext, p_w2, p_h2, asrc2, adst2, p_as2, p_ad2, Nn);
    pull2<<<(Nn + 7) / 8, 256>>>(b2, out, Nn);
}

// round 6
// speedup vs baseline: 2.1035x; 1.0101x over previous
#include <cuda_runtime.h>
#include <cuda_bf16.h>
#include <cstdint>

#define MAXN 50000
#define MAXE 900080
#define D1   256
#define H1   4
#define C2   32
#define KEXT 768          // logical K (3 segments of 256)
#define KA   512          // stored K ([hi|lo])

// ---------------- scratch (device globals) -----------------------------------
__device__ float g_h1 [MAXN * D1];
__device__ float g_as1[MAXN * H1];
__device__ float g_ad1[MAXN * H1];
__device__ float g_h2 [MAXN * C2];
__device__ float g_as2[MAXN];
__device__ float g_ad2[MAXN];
__device__ __nv_bfloat16 g_aext [MAXN * KA];   // [hi | lo]
__device__ __nv_bfloat16 g_wext1[D1 * KA];
__device__ __nv_bfloat16 g_wext2[C2 * KA];
__device__ int g_row[MAXN + 1];
__device__ int g_cur[MAXN];
__device__ int g_csr[MAXE];

// ---------------- helpers -----------------------------------------------------
__device__ __forceinline__ uint32_t smem_u32(const void* p) {
    uint32_t a;
    asm("{ .reg .u64 t; cvta.to.shared.u64 t, %1; cvt.u32.u64 %0, t; }" : "=r"(a) : "l"(p));
    return a;
}
__device__ __forceinline__ void cp_async16(uint32_t saddr, const void* gptr) {
    asm volatile("cp.async.cg.shared.global [%0], [%1], 16;"
        :: "r"(saddr), "l"(__cvta_generic_to_global(gptr)) : "memory");
}
#define CP_COMMIT asm volatile("cp.async.commit_group;" ::: "memory")
#define CP_WAIT0  asm volatile("cp.async.wait_group 0;" ::: "memory")
#define CP_WAIT1  asm volatile("cp.async.wait_group 1;" ::: "memory")

__device__ __forceinline__ void mma16816(float* c, const uint32_t* a, uint32_t b0, uint32_t b1) {
    asm volatile("mma.sync.aligned.m16n8k16.row.col.f32.bf16.bf16.f32 "
        "{%0,%1,%2,%3}, {%4,%5,%6,%7}, {%8,%9}, {%0,%1,%2,%3};"
        : "+f"(c[0]), "+f"(c[1]), "+f"(c[2]), "+f"(c[3])
        : "r"(a[0]), "r"(a[1]), "r"(a[2]), "r"(a[3]), "r"(b0), "r"(b1));
}
__device__ __forceinline__ uint32_t pack_bf16x2(float a, float b) {
    __nv_bfloat16 ha = __float2bfloat16_rn(a), hb = __float2bfloat16_rn(b);
    return (uint32_t)__bfloat16_as_ushort(ha) | ((uint32_t)__bfloat16_as_ushort(hb) << 16);
}

// ---------------- weight ext prep ([hi|lo], K=512) ----------------------------
__global__ void prep_w(const float* __restrict__ W1, const float* __restrict__ W2) {
    int idx = blockIdx.x * blockDim.x + threadIdx.x;
    if (idx < D1 * D1) {
        int k = idx >> 8, n = idx & 255;
        float w = W1[k * D1 + n];
        __nv_bfloat16 h = __float2bfloat16_rn(w);
        g_wext1[(size_t)n * KA + k]       = h;
        g_wext1[(size_t)n * KA + 256 + k] = __float2bfloat16_rn(w - __bfloat162float(h));
    } else if (idx < D1 * D1 + D1 * C2) {
        int j = idx - D1 * D1;
        int k = j >> 5, n = j & 31;
        float w = W2[k * C2 + n];
        __nv_bfloat16 h = __float2bfloat16_rn(w);
        g_wext2[(size_t)n * KA + k]       = h;
        g_wext2[(size_t)n * KA + 256 + k] = __float2bfloat16_rn(w - __bfloat162float(h));
    }
}

// ---------------- A ext prep: x -> [hi|lo] ------------------------------------
__global__ void prep_a1(const float* __restrict__ x, int Nn) {
    int idx = blockIdx.x * blockDim.x + threadIdx.x;
    if (idx >= Nn * D1) return;
    int row = idx >> 8, k = idx & 255;
    float v = x[idx];
    __nv_bfloat16 h = __float2bfloat16_rn(v);
    size_t base = (size_t)row * KA;
    g_aext[base + k]       = h;
    g_aext[base + 256 + k] = __float2bfloat16_rn(v - __bfloat162float(h));
}

// ---------------- CSR build ----------------------------------------------------
__global__ void csr_init(int Nn) {
    int i = blockIdx.x * blockDim.x + threadIdx.x;
    if (i < Nn) g_cur[i] = 1;
}
__global__ void csr_count(const int* __restrict__ ei, int E) {
    int i = blockIdx.x * blockDim.x + threadIdx.x;
    if (i < E) atomicAdd(&g_cur[ei[E + i]], 1);
}
__global__ void csr_scan(int Nn) {
    __shared__ int s[1024];
    const int t = threadIdx.x;
    const int chunk = (Nn + 1023) / 1024;
    const int beg = t * chunk;
    const int end = (beg + chunk < Nn) ? beg + chunk : Nn;
    int sum = 0;
    for (int i = beg; i < end; i++) sum += g_cur[i];
    s[t] = sum;
    __syncthreads();
    int run_in = sum;
    for (int d = 1; d < 1024; d <<= 1) {
        int v = (t >= d) ? s[t - d] : 0;
        __syncthreads();
        s[t] += v;
        __syncthreads();
    }
    int run = s[t] - run_in;
    for (int i = beg; i < end; i++) {
        int c = g_cur[i];
        g_row[i] = run;
        g_cur[i] = run;
        run += c;
    }
    if (end == Nn && beg <= Nn) g_row[Nn] = run;
}
__global__ void csr_scatter(const int* __restrict__ ei, int E, int Nn) {
    int i = blockIdx.x * blockDim.x + threadIdx.x;
    int Etot = E + Nn;
    if (i >= Etot) return;
    int src, dst;
    if (i < E) { src = ei[i]; dst = ei[E + i]; }
    else       { src = dst = i - E; }
    int pos = atomicAdd(&g_cur[dst], 1);
    g_csr[pos] = src;
}

// ---------------- HMMA GEMM: BK=32, 3-stage cp.async, 2 CTA/SM ----------------
// Logical K = 768 over stored [hi|lo] via segment map:
//   A segments per k-tile group: hi, hi, lo ; B segments: hi, lo, hi.
template<int BN>
__global__ void __launch_bounds__(256, 2)
gemm_mma(const __nv_bfloat16* __restrict__ Aext,
         const __nv_bfloat16* __restrict__ Bext,
         float* __restrict__ Cout,
         const float* __restrict__ att_s, const float* __restrict__ att_d,
         float* __restrict__ out_s, float* __restrict__ out_d, int M)
{
    constexpr int BM = 128, BK = 32, KT = KEXT / BK;   // 24 k-tiles
    constexpr int LDA = 40;                            // bf16 elems per smem row
    constexpr int WN = (BN == 128) ? 64 : 32;
    constexpr int WX = BN / WN, WY = 8 / WX;
    constexpr int MROWS = BM / WY, MT_ = MROWS / 16, NT_ = WN / 8;
    constexpr int NTOT = (BN == 128) ? 256 : 32;
    constexpr int HEADC = WN, NH = NTOT / HEADC;
    constexpr int ABYTES = BM * LDA * 2;               // 10240
    constexpr int BBYTES = BN * LDA * 2;
    constexpr int STAGE = ABYTES + BBYTES;
    constexpr int ACH = BM * BK / 8;                   // 16B chunks of A per stage
    constexpr int BCH = BN * BK / 8;

    extern __shared__ char sm[];
    float* s_as = (float*)(sm + 3 * STAGE);
    float* s_ad = s_as + NTOT;

    const int tid = threadIdx.x;
    const int lane = tid & 31, wid = tid >> 5;
    const int wx = wid % WX, wy = wid / WX;
    const int m0 = blockIdx.y * BM;
    const int n0 = blockIdx.x * BN;

    if (tid < NTOT) { s_as[tid] = att_s[tid]; s_ad[tid] = att_d[tid]; }

    const uint32_t smBase = smem_u32(sm);

    auto issue = [&](int kt, int buf) {
        int seg = kt >> 3;
        int koff = (kt & 7) * 32;
        int aoff = ((seg < 2) ? 0 : 256) + koff;
        int boff = ((seg == 1) ? 256 : 0) + koff;
        uint32_t aS = smBase + buf * STAGE;
        uint32_t bS = aS + ABYTES;
#pragma unroll
        for (int i = 0; i < ACH / 256; i++) {
            int idx = tid + i * 256;
            int r = idx >> 2, c4 = idx & 3;
            int row = m0 + r; if (row > M - 1) row = M - 1;
            cp_async16(aS + (r * LDA + c4 * 8) * 2,
                       Aext + (size_t)row * KA + aoff + c4 * 8);
        }
        if (BCH >= 256) {
#pragma unroll
            for (int i = 0; i < BCH / 256; i++) {
                int idx = tid + i * 256;
                int r = idx >> 2, c4 = idx & 3;
                cp_async16(bS + (r * LDA + c4 * 8) * 2,
                           Bext + (size_t)(n0 + r) * KA + boff + c4 * 8);
            }
        } else if (tid < BCH) {
            int r = tid >> 2, c4 = tid & 3;
            cp_async16(bS + (r * LDA + c4 * 8) * 2,
                       Bext + (size_t)(n0 + r) * KA + boff + c4 * 8);
        }
        CP_COMMIT;
    };

    float acc[MT_][NT_][4];
#pragma unroll
    for (int mt = 0; mt < MT_; mt++)
#pragma unroll
        for (int nt = 0; nt < NT_; nt++)
#pragma unroll
            for (int q = 0; q < 4; q++) acc[mt][nt][q] = 0.f;

    issue(0, 0);
    issue(1, 1);
    for (int kt = 0; kt < KT; kt++) {
        if (kt + 2 < KT) { CP_WAIT1; } else { CP_WAIT0; }
        __syncthreads();
        if (kt + 2 < KT) issue(kt + 2, (kt + 2) % 3);
        const char* Ab = sm + (kt % 3) * STAGE;
        const char* Bb = Ab + ABYTES;
#pragma unroll
        for (int ks = 0; ks < 2; ks++) {
            const int kq = ks * 16 + (lane & 3) * 2;
            uint32_t a[MT_][4];
#pragma unroll
            for (int mt = 0; mt < MT_; mt++) {
                int row = wy * MROWS + mt * 16 + (lane >> 2);
                const char* ap = Ab + (row * LDA + kq) * 2;
                a[mt][0] = *(const uint32_t*)ap;
                a[mt][2] = *(const uint32_t*)(ap + 16);
                a[mt][1] = *(const uint32_t*)(ap + 8 * LDA * 2);
                a[mt][3] = *(const uint32_t*)(ap + 8 * LDA * 2 + 16);
            }
#pragma unroll
            for (int nt = 0; nt < NT_; nt++) {
                int n = wx * WN + nt * 8 + (lane >> 2);
                const char* bp = Bb + (n * LDA + kq) * 2;
                uint32_t b0 = *(const uint32_t*)bp;
                uint32_t b1 = *(const uint32_t*)(bp + 16);
#pragma unroll
                for (int mt = 0; mt < MT_; mt++)
                    mma16816(acc[mt][nt], a[mt], b0, b1);
            }
        }
        __syncthreads();
    }

    // epilogue: store C + fused att dot products (warp covers one head)
#pragma unroll
    for (int mt = 0; mt < MT_; mt++) {
        int row = m0 + wy * MROWS + mt * 16 + (lane >> 2);
        float s0 = 0.f, d0 = 0.f, s1 = 0.f, d1 = 0.f;
#pragma unroll
        for (int nt = 0; nt < NT_; nt++) {
            int col = n0 + wx * WN + nt * 8 + (lane & 3) * 2;
            float c0 = acc[mt][nt][0], c1 = acc[mt][nt][1];
            float c2 = acc[mt][nt][2], c3 = acc[mt][nt][3];
            if (row < M)     *(float2*)&Cout[(size_t)row * NTOT + col]       = make_float2(c0, c1);
            if (row + 8 < M) *(float2*)&Cout[(size_t)(row + 8) * NTOT + col] = make_float2(c2, c3);
            s0 += c0 * s_as[col] + c1 * s_as[col + 1];
            d0 += c0 * s_ad[col] + c1 * s_ad[col + 1];
            s1 += c2 * s_as[col] + c3 * s_as[col + 1];
            d1 += c2 * s_ad[col] + c3 * s_ad[col + 1];
        }
#pragma unroll
        for (int off = 1; off <= 2; off <<= 1) {
            s0 += __shfl_xor_sync(0xffffffffu, s0, off);
            d0 += __shfl_xor_sync(0xffffffffu, d0, off);
            s1 += __shfl_xor_sync(0xffffffffu, s1, off);
            d1 += __shfl_xor_sync(0xffffffffu, d1, off);
        }
        if ((lane & 3) == 0) {
            int head = (n0 + wx * WN) / HEADC;
            if (row < M)     { out_s[row * NH + head] = s0;       out_d[row * NH + head] = d0; }
            if (row + 8 < M) { out_s[(row + 8) * NH + head] = s1; out_d[(row + 8) * NH + head] = d1; }
        }
    }
}

// ---------------- layer-1 pull: warp per dst node ------------------------------
__global__ void __launch_bounds__(256)
pull1(const float* __restrict__ b1, int Nn) {
    int warp = (blockIdx.x * blockDim.x + threadIdx.x) >> 5;
    int lane = threadIdx.x & 31;
    if (warp >= Nn) return;
    const int d = warp;
    const int base = g_row[d], end = g_row[d + 1];

    float adl = (lane < H1) ? g_ad1[d * H1 + lane] : 0.f;
    float4 acc1 = make_float4(0.f, 0.f, 0.f, 0.f);
    float4 acc2 = make_float4(0.f, 0.f, 0.f, 0.f);
    float den = 0.f;

    int src_next = g_csr[base];
    for (int i = base; i < end; i++) {
        int src = src_next;
        if (i + 1 < end) src_next = g_csr[i + 1];
        float p = 0.f;
        if (lane < H1) {
            float e = __ldg(&g_as1[src * H1 + lane]) + adl;
            e = (e >= 0.f) ? e : 0.2f * e;
            p = __expf(e);
            den += p;
        }
        float pa = __shfl_sync(0xffffffffu, p, lane >> 4);
        float pb = __shfl_sync(0xffffffffu, p, 2 + (lane >> 4));
        const float4* h4 = (const float4*)(g_h1 + (size_t)src * D1);
        float4 v1 = __ldg(h4 + lane);
        float4 v2 = __ldg(h4 + lane + 32);
        acc1.x += pa * v1.x; acc1.y += pa * v1.y; acc1.z += pa * v1.z; acc1.w += pa * v1.w;
        acc2.x += pb * v2.x; acc2.y += pb * v2.y; acc2.z += pb * v2.z; acc2.w += pb * v2.w;
    }

    float dena = __shfl_sync(0xffffffffu, den, lane >> 4);
    float denb = __shfl_sync(0xffffffffu, den, 2 + (lane >> 4));
    float inva = 1.f / dena, invb = 1.f / denb;

    size_t abase = (size_t)d * KA;
    int c1 = 4 * lane, c2 = 128 + 4 * lane;
    float v[8];
    v[0] = acc1.x * inva + __ldg(&b1[c1]);
    v[1] = acc1.y * inva + __ldg(&b1[c1 + 1]);
    v[2] = acc1.z * inva + __ldg(&b1[c1 + 2]);
    v[3] = acc1.w * inva + __ldg(&b1[c1 + 3]);
    v[4] = acc2.x * invb + __ldg(&b1[c2]);
    v[5] = acc2.y * invb + __ldg(&b1[c2 + 1]);
    v[6] = acc2.z * invb + __ldg(&b1[c2 + 2]);
    v[7] = acc2.w * invb + __ldg(&b1[c2 + 3]);
#pragma unroll
    for (int q = 0; q < 8; q++) v[q] = (v[q] > 0.f) ? v[q] : (__expf(v[q]) - 1.f);

#pragma unroll
    for (int g = 0; g < 2; g++) {
        int c = g ? c2 : c1;
        float a0 = v[4 * g], a1 = v[4 * g + 1], a2 = v[4 * g + 2], a3 = v[4 * g + 3];
        __nv_bfloat16 hb0 = __float2bfloat16_rn(a0), hb1 = __float2bfloat16_rn(a1);
        __nv_bfloat16 hb2 = __float2bfloat16_rn(a2), hb3 = __float2bfloat16_rn(a3);
        *(uint32_t*)&g_aext[abase + c]           = pack_bf16x2(a0, a1);
        *(uint32_t*)&g_aext[abase + c + 2]       = pack_bf16x2(a2, a3);
        *(uint32_t*)&g_aext[abase + 256 + c]     = pack_bf16x2(a0 - __bfloat162float(hb0), a1 - __bfloat162float(hb1));
        *(uint32_t*)&g_aext[abase + 256 + c + 2] = pack_bf16x2(a2 - __bfloat162float(hb2), a3 - __bfloat162float(hb3));
    }
}

// ---------------- layer-2 pull: warp per dst node, writes final output --------
__global__ void __launch_bounds__(256)
pull2(const float* __restrict__ b2, float* __restrict__ out, int Nn) {
    int warp = (blockIdx.x * blockDim.x + threadIdx.x) >> 5;
    int lane = threadIdx.x & 31;
    if (warp >= Nn) return;
    const int d = warp;
    const int base = g_row[d], end = g_row[d + 1];

    float ad = g_ad2[d];
    float acc = 0.f, den = 0.f;

    int src_next = g_csr[base];
    for (int i = base; i < end; i++) {
        int src = src_next;
        if (i + 1 < end) src_next = g_csr[i + 1];
        float p = 0.f;
        if (lane == 0) {
            float e = __ldg(&g_as2[src]) + ad;
            e = (e >= 0.f) ? e : 0.2f * e;
            p = __expf(e);
        }
        p = __shfl_sync(0xffffffffu, p, 0);
        den += p;
        acc += p * __ldg(&g_h2[(size_t)src * C2 + lane]);
    }
    out[(size_t)d * C2 + lane] = acc / den + __ldg(&b2[lane]);
}

// ---------------- host orchestration ------------------------------------------
extern "C" void kernel_launch(void* const* d_in, const int* in_sizes, int n_in,
                              void* d_out, int out_size) {
    const float* x     = (const float*)d_in[0];
    const int*   ei    = (const int*)  d_in[1];
    const float* W1    = (const float*)d_in[2];
    const float* asrc1 = (const float*)d_in[3];
    const float* adst1 = (const float*)d_in[4];
    const float* b1    = (const float*)d_in[5];
    const float* W2    = (const float*)d_in[6];
    const float* asrc2 = (const float*)d_in[7];
    const float* adst2 = (const float*)d_in[8];
    const float* b2    = (const float*)d_in[9];
    float* out = (float*)d_out;

    const int Nn = in_sizes[0] / D1;
    const int E  = in_sizes[1] / 2;
    const int Etot = E + Nn;
    const int MT = (Nn + 127) / 128;

    __nv_bfloat16 *p_aext, *p_w1, *p_w2;
    float *p_h1, *p_h2, *p_as1, *p_ad1, *p_as2, *p_ad2;
    cudaGetSymbolAddress((void**)&p_aext, g_aext);
    cudaGetSymbolAddress((void**)&p_w1,   g_wext1);
    cudaGetSymbolAddress((void**)&p_w2,   g_wext2);
    cudaGetSymbolAddress((void**)&p_h1,   g_h1);
    cudaGetSymbolAddress((void**)&p_h2,   g_h2);
    cudaGetSymbolAddress((void**)&p_as1,  g_as1);
    cudaGetSymbolAddress((void**)&p_ad1,  g_ad1);
    cudaGetSymbolAddress((void**)&p_as2,  g_as2);
    cudaGetSymbolAddress((void**)&p_ad2,  g_ad2);

    constexpr int SM1 = 3 * (128 * 40 * 2 + 128 * 40 * 2) + 2 * 256 * 4;  // 63488
    constexpr int SM2 = 3 * (128 * 40 * 2 + 32 * 40 * 2)  + 2 * 32 * 4;   // 38656
    cudaFuncSetAttribute(gemm_mma<128>, cudaFuncAttributeMaxDynamicSharedMemorySize, SM1);
    cudaFuncSetAttribute(gemm_mma<32>,  cudaFuncAttributeMaxDynamicSharedMemorySize, SM2);

    csr_init   <<<(Nn + 255) / 256, 256>>>(Nn);
    csr_count  <<<(E + 255) / 256, 256>>>(ei, E);
    csr_scan   <<<1, 1024>>>(Nn);
    csr_scatter<<<(Etot + 255) / 256, 256>>>(ei, E, Nn);

    prep_w <<<(D1 * D1 + D1 * C2 + 255) / 256, 256>>>(W1, W2);
    prep_a1<<<(Nn * D1 + 255) / 256, 256>>>(x, Nn);

    gemm_mma<128><<<dim3(2, MT), 256, SM1>>>(p_aext, p_w1, p_h1, asrc1, adst1, p_as1, p_ad1, Nn);
    pull1<<<(Nn + 7) / 8, 256>>>(b1, Nn);
    gemm_mma<32><<<dim3(1, MT), 256, SM2>>>(p_aext, p_w2, p_h2, asrc2, adst2, p_as2, p_ad2, Nn);
    pull2<<<(Nn + 7) / 8, 256>>>(b2, out, Nn);
}

// round 7
// speedup vs baseline: 2.1658x; 1.0296x over previous
#include <cuda_runtime.h>
#include <cuda_bf16.h>
#include <cstdint>

#define MAXN 50000
#define MAXE 900080
#define D1   256
#define H1   4
#define C2   32
#define KEXT 768          // logical K (3 segments of 256)
#define KA   512          // stored K ([hi|lo])

// ---------------- scratch (device globals) -----------------------------------
__device__ float g_h1 [MAXN * D1];
__device__ float g_as1[MAXN * H1];
__device__ float g_ad1[MAXN * H1];
__device__ float g_h2 [MAXN * C2];
__device__ float g_as2[MAXN];
__device__ float g_ad2[MAXN];
__device__ __nv_bfloat16 g_aext [MAXN * KA];   // [hi | lo]
__device__ __nv_bfloat16 g_wext1[D1 * KA];
__device__ __nv_bfloat16 g_wext2[C2 * KA];
__device__ int g_row[MAXN + 1];
__device__ int g_cur[MAXN];    // INVARIANT: all-zero between kernel_launch calls
__device__ int g_csr[MAXE];

// ---------------- helpers -----------------------------------------------------
__device__ __forceinline__ uint32_t smem_u32(const void* p) {
    uint32_t a;
    asm("{ .reg .u64 t; cvta.to.shared.u64 t, %1; cvt.u32.u64 %0, t; }" : "=r"(a) : "l"(p));
    return a;
}
__device__ __forceinline__ void cp_async16(uint32_t saddr, const void* gptr) {
    asm volatile("cp.async.cg.shared.global [%0], [%1], 16;"
        :: "r"(saddr), "l"(__cvta_generic_to_global(gptr)) : "memory");
}
#define CP_COMMIT asm volatile("cp.async.commit_group;" ::: "memory")
#define CP_WAIT0  asm volatile("cp.async.wait_group 0;" ::: "memory")
#define CP_WAIT1  asm volatile("cp.async.wait_group 1;" ::: "memory")

__device__ __forceinline__ void mma16816(float* c, const uint32_t* a, uint32_t b0, uint32_t b1) {
    asm volatile("mma.sync.aligned.m16n8k16.row.col.f32.bf16.bf16.f32 "
        "{%0,%1,%2,%3}, {%4,%5,%6,%7}, {%8,%9}, {%0,%1,%2,%3};"
        : "+f"(c[0]), "+f"(c[1]), "+f"(c[2]), "+f"(c[3])
        : "r"(a[0]), "r"(a[1]), "r"(a[2]), "r"(a[3]), "r"(b0), "r"(b1));
}
__device__ __forceinline__ void ldmatrix4(uint32_t* r, uint32_t addr) {
    asm volatile("ldmatrix.sync.aligned.m8n8.x4.shared.b16 {%0,%1,%2,%3}, [%4];"
        : "=r"(r[0]), "=r"(r[1]), "=r"(r[2]), "=r"(r[3]) : "r"(addr));
}
__device__ __forceinline__ uint32_t pack_bf16x2(float a, float b) {
    __nv_bfloat16 ha = __float2bfloat16_rn(a), hb = __float2bfloat16_rn(b);
    return (uint32_t)__bfloat16_as_ushort(ha) | ((uint32_t)__bfloat16_as_ushort(hb) << 16);
}

// ---------------- fused prep: W-ext + A-ext + degree count --------------------
__global__ void fused_prep(const float* __restrict__ x, const float* __restrict__ W1,
                           const float* __restrict__ W2, const int* __restrict__ ei,
                           int Nn, int E) {
    int idx = blockIdx.x * blockDim.x + threadIdx.x;
    if (idx < D1 * D1) {
        int k = idx >> 8, n = idx & 255;
        float w = W1[k * D1 + n];
        __nv_bfloat16 h = __float2bfloat16_rn(w);
        g_wext1[(size_t)n * KA + k]       = h;
        g_wext1[(size_t)n * KA + 256 + k] = __float2bfloat16_rn(w - __bfloat162float(h));
        return;
    }
    idx -= D1 * D1;
    if (idx < D1 * C2) {
        int k = idx >> 5, n = idx & 31;
        float w = W2[k * C2 + n];
        __nv_bfloat16 h = __float2bfloat16_rn(w);
        g_wext2[(size_t)n * KA + k]       = h;
        g_wext2[(size_t)n * KA + 256 + k] = __float2bfloat16_rn(w - __bfloat162float(h));
        return;
    }
    idx -= D1 * C2;
    if (idx < E) { atomicAdd(&g_cur[ei[E + idx]], 1); return; }
    idx -= E;
    if (idx < Nn * D1) {
        int row = idx >> 8, k = idx & 255;
        float v = x[idx];
        __nv_bfloat16 h = __float2bfloat16_rn(v);
        size_t base = (size_t)row * KA;
        g_aext[base + k]       = h;
        g_aext[base + 256 + k] = __float2bfloat16_rn(v - __bfloat162float(h));
    }
}

// ---------------- CSR scan (+1 self loop per node) ----------------------------
__global__ void csr_scan(int Nn) {
    __shared__ int s[1024];
    const int t = threadIdx.x;
    const int chunk = (Nn + 1023) / 1024;
    const int beg = t * chunk;
    const int end = (beg + chunk < Nn) ? beg + chunk : Nn;
    int sum = 0;
    for (int i = beg; i < end; i++) sum += g_cur[i] + 1;
    s[t] = sum;
    __syncthreads();
    int run_in = sum;
    for (int d = 1; d < 1024; d <<= 1) {
        int v = (t >= d) ? s[t - d] : 0;
        __syncthreads();
        s[t] += v;
        __syncthreads();
    }
    int run = s[t] - run_in;
    for (int i = beg; i < end; i++) {
        int c = g_cur[i] + 1;
        g_row[i] = run;
        g_cur[i] = run;
        run += c;
    }
    if (end == Nn && beg <= Nn) g_row[Nn] = run;
}
__global__ void csr_scatter(const int* __restrict__ ei, int E, int Nn) {
    int i = blockIdx.x * blockDim.x + threadIdx.x;
    int Etot = E + Nn;
    if (i >= Etot) return;
    int src, dst;
    if (i < E) { src = ei[i]; dst = ei[E + i]; }
    else       { src = dst = i - E; }
    int pos = atomicAdd(&g_cur[dst], 1);
    g_csr[pos] = src;
}

// ---------------- HMMA GEMM: ldmatrix frags, BK=32, 3-stage -------------------
template<int BN>
__global__ void __launch_bounds__(256, 2)
gemm_mma(const __nv_bfloat16* __restrict__ Aext,
         const __nv_bfloat16* __restrict__ Bext,
         float* __restrict__ Cout,
         const float* __restrict__ att_s, const float* __restrict__ att_d,
         float* __restrict__ out_s, float* __restrict__ out_d, int M)
{
    constexpr int BM = 128, BK = 32, KT = KEXT / BK;   // 24 k-tiles
    constexpr int LDA = 40;
    constexpr int WN = (BN == 128) ? 64 : 32;
    constexpr int WX = BN / WN, WY = 8 / WX;
    constexpr int MROWS = BM / WY, MT_ = MROWS / 16, NT_ = WN / 8;
    constexpr int NPAIR = NT_ / 2;
    constexpr int NTOT = (BN == 128) ? 256 : 32;
    constexpr int HEADC = WN, NH = NTOT / HEADC;
    constexpr int ABYTES = BM * LDA * 2;
    constexpr int BBYTES = BN * LDA * 2;
    constexpr int STAGE = ABYTES + BBYTES;
    constexpr int ACH = BM * BK / 8;
    constexpr int BCH = BN * BK / 8;

    extern __shared__ char sm[];
    float* s_as = (float*)(sm + 3 * STAGE);
    float* s_ad = s_as + NTOT;

    const int tid = threadIdx.x;
    const int lane = tid & 31, wid = tid >> 5;
    const int wx = wid % WX, wy = wid / WX;
    const int m0 = blockIdx.y * BM;
    const int n0 = blockIdx.x * BN;

    if (tid < NTOT) { s_as[tid] = att_s[tid]; s_ad[tid] = att_d[tid]; }

    const uint32_t smBase = smem_u32(sm);

    auto issue = [&](int kt, int buf) {
        int seg = kt >> 3;
        int koff = (kt & 7) * 32;
        int aoff = ((seg < 2) ? 0 : 256) + koff;
        int boff = ((seg == 1) ? 256 : 0) + koff;
        uint32_t aS = smBase + buf * STAGE;
        uint32_t bS = aS + ABYTES;
#pragma unroll
        for (int i = 0; i < ACH / 256; i++) {
            int idx = tid + i * 256;
            int r = idx >> 2, c4 = idx & 3;
            int row = m0 + r; if (row > M - 1) row = M - 1;
            cp_async16(aS + (r * LDA + c4 * 8) * 2,
                       Aext + (size_t)row * KA + aoff + c4 * 8);
        }
        if (BCH >= 256) {
#pragma unroll
            for (int i = 0; i < BCH / 256; i++) {
                int idx = tid + i * 256;
                int r = idx >> 2, c4 = idx & 3;
                cp_async16(bS + (r * LDA + c4 * 8) * 2,
                           Bext + (size_t)(n0 + r) * KA + boff + c4 * 8);
            }
        } else if (tid < BCH) {
            int r = tid >> 2, c4 = tid & 3;
            cp_async16(bS + (r * LDA + c4 * 8) * 2,
                       Bext + (size_t)(n0 + r) * KA + boff + c4 * 8);
        }
        CP_COMMIT;
    };

    float acc[MT_][NT_][4];
#pragma unroll
    for (int mt = 0; mt < MT_; mt++)
#pragma unroll
        for (int nt = 0; nt < NT_; nt++)
#pragma unroll
            for (int q = 0; q < 4; q++) acc[mt][nt][q] = 0.f;

    // ldmatrix per-lane offsets
    const int aRow = lane & 15;                 // rows 0-15 (groups 0,1 then 2,3)
    const int aCol = (lane & 16) >> 1;          // +8 k for groups 2,3
    const int bRow = (lane & 7) + ((lane & 16) >> 1);  // n-rows: g0,g1->0-7; g2,g3->8-15
    const int bCol = lane & 8;                  // +8 k for groups 1,3

    issue(0, 0);
    issue(1, 1);
    for (int kt = 0; kt < KT; kt++) {
        if (kt + 2 < KT) { CP_WAIT1; } else { CP_WAIT0; }
        __syncthreads();
        if (kt + 2 < KT) issue(kt + 2, (kt + 2) % 3);
        uint32_t AbU = smBase + (kt % 3) * STAGE;
        uint32_t BbU = AbU + ABYTES;
#pragma unroll
        for (int ks = 0; ks < 2; ks++) {
            const int kq0 = ks * 16;
            uint32_t a[MT_][4];
#pragma unroll
            for (int mt = 0; mt < MT_; mt++)
                ldmatrix4(a[mt], AbU + (((wy * MROWS + mt * 16 + aRow) * LDA + kq0 + aCol) << 1));
#pragma unroll
            for (int np = 0; np < NPAIR; np++) {
                uint32_t b[4];
                ldmatrix4(b, BbU + (((wx * WN + np * 16 + bRow) * LDA + kq0 + bCol) << 1));
#pragma unroll
                for (int mt = 0; mt < MT_; mt++) {
                    mma16816(acc[mt][2 * np],     a[mt], b[0], b[1]);
                    mma16816(acc[mt][2 * np + 1], a[mt], b[2], b[3]);
                }
            }
        }
        __syncthreads();
    }

    // epilogue: store C + fused att dot products (warp covers one head)
#pragma unroll
    for (int mt = 0; mt < MT_; mt++) {
        int row = m0 + wy * MROWS + mt * 16 + (lane >> 2);
        float s0 = 0.f, d0 = 0.f, s1 = 0.f, d1 = 0.f;
#pragma unroll
        for (int nt = 0; nt < NT_; nt++) {
            int col = n0 + wx * WN + nt * 8 + (lane & 3) * 2;
            float c0 = acc[mt][nt][0], c1 = acc[mt][nt][1];
            float c2 = acc[mt][nt][2], c3 = acc[mt][nt][3];
            if (row < M)     *(float2*)&Cout[(size_t)row * NTOT + col]       = make_float2(c0, c1);
            if (row + 8 < M) *(float2*)&Cout[(size_t)(row + 8) * NTOT + col] = make_float2(c2, c3);
            s0 += c0 * s_as[col] + c1 * s_as[col + 1];
            d0 += c0 * s_ad[col] + c1 * s_ad[col + 1];
            s1 += c2 * s_as[col] + c3 * s_as[col + 1];
            d1 += c2 * s_ad[col] + c3 * s_ad[col + 1];
        }
#pragma unroll
        for (int off = 1; off <= 2; off <<= 1) {
            s0 += __shfl_xor_sync(0xffffffffu, s0, off);
            d0 += __shfl_xor_sync(0xffffffffu, d0, off);
            s1 += __shfl_xor_sync(0xffffffffu, s1, off);
            d1 += __shfl_xor_sync(0xffffffffu, d1, off);
        }
        if ((lane & 3) == 0) {
            int head = (n0 + wx * WN) / HEADC;
            if (row < M)     { out_s[row * NH + head] = s0;       out_d[row * NH + head] = d0; }
            if (row + 8 < M) { out_s[(row + 8) * NH + head] = s1; out_d[(row + 8) * NH + head] = d1; }
        }
    }
}

// ---------------- layer-1 pull: warp per dst node (+g_cur reset) --------------
__global__ void __launch_bounds__(256)
pull1(const float* __restrict__ b1, int Nn) {
    int warp = (blockIdx.x * blockDim.x + threadIdx.x) >> 5;
    int lane = threadIdx.x & 31;
    if (warp >= Nn) return;
    const int d = warp;
    const int base = g_row[d], end = g_row[d + 1];
    if (lane == 0) g_cur[d] = 0;     // restore all-zero invariant for next call

    float adl = (lane < H1) ? g_ad1[d * H1 + lane] : 0.f;
    float4 acc1 = make_float4(0.f, 0.f, 0.f, 0.f);
    float4 acc2 = make_float4(0.f, 0.f, 0.f, 0.f);
    float den = 0.f;

    int src_next = g_csr[base];
    for (int i = base; i < end; i++) {
        int src = src_next;
        if (i + 1 < end) src_next = g_csr[i + 1];
        float p = 0.f;
        if (lane < H1) {
            float e = __ldg(&g_as1[src * H1 + lane]) + adl;
            e = (e >= 0.f) ? e : 0.2f * e;
            p = __expf(e);
            den += p;
        }
        float pa = __shfl_sync(0xffffffffu, p, lane >> 4);
        float pb = __shfl_sync(0xffffffffu, p, 2 + (lane >> 4));
        const float4* h4 = (const float4*)(g_h1 + (size_t)src * D1);
        float4 v1 = __ldg(h4 + lane);
        float4 v2 = __ldg(h4 + lane + 32);
        acc1.x += pa * v1.x; acc1.y += pa * v1.y; acc1.z += pa * v1.z; acc1.w += pa * v1.w;
        acc2.x += pb * v2.x; acc2.y += pb * v2.y; acc2.z += pb * v2.z; acc2.w += pb * v2.w;
    }

    float dena = __shfl_sync(0xffffffffu, den, lane >> 4);
    float denb = __shfl_sync(0xffffffffu, den, 2 + (lane >> 4));
    float inva = 1.f / dena, invb = 1.f / denb;

    size_t abase = (size_t)d * KA;
    int c1 = 4 * lane, c2 = 128 + 4 * lane;
    float v[8];
    v[0] = acc1.x * inva + __ldg(&b1[c1]);
    v[1] = acc1.y * inva + __ldg(&b1[c1 + 1]);
    v[2] = acc1.z * inva + __ldg(&b1[c1 + 2]);
    v[3] = acc1.w * inva + __ldg(&b1[c1 + 3]);
    v[4] = acc2.x * invb + __ldg(&b1[c2]);
    v[5] = acc2.y * invb + __ldg(&b1[c2 + 1]);
    v[6] = acc2.z * invb + __ldg(&b1[c2 + 2]);
    v[7] = acc2.w * invb + __ldg(&b1[c2 + 3]);
#pragma unroll
    for (int q = 0; q < 8; q++) v[q] = (v[q] > 0.f) ? v[q] : (__expf(v[q]) - 1.f);

#pragma unroll
    for (int g = 0; g < 2; g++) {
        int c = g ? c2 : c1;
        float a0 = v[4 * g], a1 = v[4 * g + 1], a2 = v[4 * g + 2], a3 = v[4 * g + 3];
        __nv_bfloat16 hb0 = __float2bfloat16_rn(a0), hb1 = __float2bfloat16_rn(a1);
        __nv_bfloat16 hb2 = __float2bfloat16_rn(a2), hb3 = __float2bfloat16_rn(a3);
        *(uint32_t*)&g_aext[abase + c]           = pack_bf16x2(a0, a1);
        *(uint32_t*)&g_aext[abase + c + 2]       = pack_bf16x2(a2, a3);
        *(uint32_t*)&g_aext[abase + 256 + c]     = pack_bf16x2(a0 - __bfloat162float(hb0), a1 - __bfloat162float(hb1));
        *(uint32_t*)&g_aext[abase + 256 + c + 2] = pack_bf16x2(a2 - __bfloat162float(hb2), a3 - __bfloat162float(hb3));
    }
}

// ---------------- layer-2 pull: warp per dst node, writes final output --------
__global__ void __launch_bounds__(256)
pull2(const float* __restrict__ b2, float* __restrict__ out, int Nn) {
    int warp = (blockIdx.x * blockDim.x + threadIdx.x) >> 5;
    int lane = threadIdx.x & 31;
    if (warp >= Nn) return;
    const int d = warp;
    const int base = g_row[d], end = g_row[d + 1];

    float ad = g_ad2[d];
    float acc = 0.f, den = 0.f;

    int src_next = g_csr[base];
    for (int i = base; i < end; i++) {
        int src = src_next;
        if (i + 1 < end) src_next = g_csr[i + 1];
        float p = 0.f;
        if (lane == 0) {
            float e = __ldg(&g_as2[src]) + ad;
            e = (e >= 0.f) ? e : 0.2f * e;
            p = __expf(e);
        }
        p = __shfl_sync(0xffffffffu, p, 0);
        den += p;
        acc += p * __ldg(&g_h2[(size_t)src * C2 + lane]);
    }
    out[(size_t)d * C2 + lane] = acc / den + __ldg(&b2[lane]);
}

// ---------------- host orchestration ------------------------------------------
extern "C" void kernel_launch(void* const* d_in, const int* in_sizes, int n_in,
                              void* d_out, int out_size) {
    const float* x     = (const float*)d_in[0];
    const int*   ei    = (const int*)  d_in[1];
    const float* W1    = (const float*)d_in[2];
    const float* asrc1 = (const float*)d_in[3];
    const float* adst1 = (const float*)d_in[4];
    const float* b1    = (const float*)d_in[5];
    const float* W2    = (const float*)d_in[6];
    const float* asrc2 = (const float*)d_in[7];
    const float* adst2 = (const float*)d_in[8];
    const float* b2    = (const float*)d_in[9];
    float* out = (float*)d_out;

    const int Nn = in_sizes[0] / D1;
    const int E  = in_sizes[1] / 2;
    const int Etot = E + Nn;
    const int MT = (Nn + 127) / 128;

    __nv_bfloat16 *p_aext, *p_w1, *p_w2;
    float *p_h1, *p_h2, *p_as1, *p_ad1, *p_as2, *p_ad2;
    cudaGetSymbolAddress((void**)&p_aext, g_aext);
    cudaGetSymbolAddress((void**)&p_w1,   g_wext1);
    cudaGetSymbolAddress((void**)&p_w2,   g_wext2);
    cudaGetSymbolAddress((void**)&p_h1,   g_h1);
    cudaGetSymbolAddress((void**)&p_h2,   g_h2);
    cudaGetSymbolAddress((void**)&p_as1,  g_as1);
    cudaGetSymbolAddress((void**)&p_ad1,  g_ad1);
    cudaGetSymbolAddress((void**)&p_as2,  g_as2);
    cudaGetSymbolAddress((void**)&p_ad2,  g_ad2);

    constexpr int SM1 = 3 * (128 * 40 * 2 + 128 * 40 * 2) + 2 * 256 * 4;
    constexpr int SM2 = 3 * (128 * 40 * 2 + 32 * 40 * 2)  + 2 * 32 * 4;
    cudaFuncSetAttribute(gemm_mma<128>, cudaFuncAttributeMaxDynamicSharedMemorySize, SM1);
    cudaFuncSetAttribute(gemm_mma<32>,  cudaFuncAttributeMaxDynamicSharedMemorySize, SM2);

    const int prep_items = D1 * D1 + D1 * C2 + E + Nn * D1;
    fused_prep <<<(prep_items + 255) / 256, 256>>>(x, W1, W2, ei, Nn, E);
    csr_scan   <<<1, 1024>>>(Nn);
    csr_scatter<<<(Etot + 255) / 256, 256>>>(ei, E, Nn);

    gemm_mma<128><<<dim3(2, MT), 256, SM1>>>(p_aext, p_w1, p_h1, asrc1, adst1, p_as1, p_ad1, Nn);
    pull1<<<(Nn + 7) / 8, 256>>>(b1, Nn);
    gemm_mma<32><<<dim3(1, MT), 256, SM2>>>(p_aext, p_w2, p_h2, asrc2, adst2, p_as2, p_ad2, Nn);
    pull2<<<(Nn + 7) / 8, 256>>>(b2, out, Nn);
}

// round 8
// speedup vs baseline: 2.9433x; 1.3590x over previous
#include <cuda_runtime.h>
#include <cuda_bf16.h>
#include <cstdint>

#define MAXN 50000
#define MAXE 900080
#define D1   256
#define H1   4
#define C2   32
#define KEXT 768          // logical K (3 segments of 256)
#define KA   512          // stored K ([hi|lo])

// ---------------- scratch (device globals) -----------------------------------
__device__ float g_h1 [MAXN * D1];
__device__ float g_as1[MAXN * H1];
__device__ float g_ad1[MAXN * H1];
__device__ float g_h2 [MAXN * C2];
__device__ float g_as2[MAXN];
__device__ float g_ad2[MAXN];
__device__ __nv_bfloat16 g_aext [MAXN * KA];   // [hi | lo]
__device__ __nv_bfloat16 g_wext1[D1 * KA];
__device__ __nv_bfloat16 g_wext2[C2 * KA];
__device__ int g_row[MAXN + 1];
__device__ int g_cur[MAXN];    // INVARIANT: all-zero between kernel_launch calls
__device__ int g_csr[MAXE];

// ---------------- helpers -----------------------------------------------------
__device__ __forceinline__ uint32_t smem_u32(const void* p) {
    uint32_t a;
    asm("{ .reg .u64 t; cvta.to.shared.u64 t, %1; cvt.u32.u64 %0, t; }" : "=r"(a) : "l"(p));
    return a;
}
__device__ __forceinline__ void cp_async16(uint32_t saddr, const void* gptr) {
    asm volatile("cp.async.cg.shared.global [%0], [%1], 16;"
        :: "r"(saddr), "l"(__cvta_generic_to_global(gptr)) : "memory");
}
#define CP_COMMIT asm volatile("cp.async.commit_group;" ::: "memory")
#define CP_WAIT0  asm volatile("cp.async.wait_group 0;" ::: "memory")
#define CP_WAIT1  asm volatile("cp.async.wait_group 1;" ::: "memory")

__device__ __forceinline__ void mma16816(float* c, const uint32_t* a, uint32_t b0, uint32_t b1) {
    asm volatile("mma.sync.aligned.m16n8k16.row.col.f32.bf16.bf16.f32 "
        "{%0,%1,%2,%3}, {%4,%5,%6,%7}, {%8,%9}, {%0,%1,%2,%3};"
        : "+f"(c[0]), "+f"(c[1]), "+f"(c[2]), "+f"(c[3])
        : "r"(a[0]), "r"(a[1]), "r"(a[2]), "r"(a[3]), "r"(b0), "r"(b1));
}
__device__ __forceinline__ void ldmatrix4(uint32_t* r, uint32_t addr) {
    asm volatile("ldmatrix.sync.aligned.m8n8.x4.shared.b16 {%0,%1,%2,%3}, [%4];"
        : "=r"(r[0]), "=r"(r[1]), "=r"(r[2]), "=r"(r[3]) : "r"(addr));
}
__device__ __forceinline__ uint32_t pack_bf16x2(float a, float b) {
    __nv_bfloat16 ha = __float2bfloat16_rn(a), hb = __float2bfloat16_rn(b);
    return (uint32_t)__bfloat16_as_ushort(ha) | ((uint32_t)__bfloat16_as_ushort(hb) << 16);
}
__device__ __forceinline__ uint32_t pack_bf16x2_lo(float a, float b) {
    __nv_bfloat16 ha = __float2bfloat16_rn(a), hb = __float2bfloat16_rn(b);
    return pack_bf16x2(a - __bfloat162float(ha), b - __bfloat162float(hb));
}

// ---------------- prep: W-ext + A-ext (vectorized) ----------------------------
__global__ void prep_wa(const float* __restrict__ x, const float* __restrict__ W1,
                        const float* __restrict__ W2, int Nn) {
    int idx = blockIdx.x * blockDim.x + threadIdx.x;
    if (idx < D1 * D1) {
        int k = idx >> 8, n = idx & 255;
        float w = W1[k * D1 + n];
        __nv_bfloat16 h = __float2bfloat16_rn(w);
        g_wext1[(size_t)n * KA + k]       = h;
        g_wext1[(size_t)n * KA + 256 + k] = __float2bfloat16_rn(w - __bfloat162float(h));
        return;
    }
    idx -= D1 * D1;
    if (idx < D1 * C2) {
        int k = idx >> 5, n = idx & 31;
        float w = W2[k * C2 + n];
        __nv_bfloat16 h = __float2bfloat16_rn(w);
        g_wext2[(size_t)n * KA + k]       = h;
        g_wext2[(size_t)n * KA + 256 + k] = __float2bfloat16_rn(w - __bfloat162float(h));
        return;
    }
    idx -= D1 * C2;
    if (idx < (Nn * D1) / 4) {
        int row = idx / (D1 / 4), c4 = idx % (D1 / 4);
        float4 v = __ldg((const float4*)(x + (size_t)row * D1) + c4);
        size_t base = (size_t)row * KA + 4 * c4;
        *(uint2*)&g_aext[base]       = make_uint2(pack_bf16x2(v.x, v.y),    pack_bf16x2(v.z, v.w));
        *(uint2*)&g_aext[base + 256] = make_uint2(pack_bf16x2_lo(v.x, v.y), pack_bf16x2_lo(v.z, v.w));
    }
}

// ---------------- CSR build (runs on forked stream) ---------------------------
__global__ void csr_count(const int* __restrict__ ei, int E) {
    int i = blockIdx.x * blockDim.x + threadIdx.x;
    if (i < E) atomicAdd(&g_cur[ei[E + i]], 1);
}
__global__ void csr_scan(int Nn) {
    __shared__ int s[1024];
    const int t = threadIdx.x;
    const int chunk = (Nn + 1023) / 1024;
    const int beg = t * chunk;
    const int end = (beg + chunk < Nn) ? beg + chunk : Nn;
    int sum = 0;
    for (int i = beg; i < end; i++) sum += g_cur[i] + 1;   // +1 self loop
    s[t] = sum;
    __syncthreads();
    int run_in = sum;
    for (int d = 1; d < 1024; d <<= 1) {
        int v = (t >= d) ? s[t - d] : 0;
        __syncthreads();
        s[t] += v;
        __syncthreads();
    }
    int run = s[t] - run_in;
    for (int i = beg; i < end; i++) {
        int c = g_cur[i] + 1;
        g_row[i] = run;
        g_cur[i] = run;
        run += c;
    }
    if (end == Nn && beg <= Nn) g_row[Nn] = run;
}
__global__ void csr_scatter(const int* __restrict__ ei, int E, int Nn) {
    int i = blockIdx.x * blockDim.x + threadIdx.x;
    int Etot = E + Nn;
    if (i >= Etot) return;
    int src, dst;
    if (i < E) { src = ei[i]; dst = ei[E + i]; }
    else       { src = dst = i - E; }
    int pos = atomicAdd(&g_cur[dst], 1);
    g_csr[pos] = src;
}

// ---------------- HMMA GEMM: ldmatrix frags, BK=32, 3-stage, 1 sync/kt --------
template<int BN>
__global__ void __launch_bounds__(256, 2)
gemm_mma(const __nv_bfloat16* __restrict__ Aext,
         const __nv_bfloat16* __restrict__ Bext,
         float* __restrict__ Cout,
         const float* __restrict__ att_s, const float* __restrict__ att_d,
         float* __restrict__ out_s, float* __restrict__ out_d, int M)
{
    constexpr int BM = 128, BK = 32, KT = KEXT / BK;   // 24 k-tiles
    constexpr int LDA = 40;
    constexpr int WN = (BN == 128) ? 64 : 32;
    constexpr int WX = BN / WN, WY = 8 / WX;
    constexpr int MROWS = BM / WY, MT_ = MROWS / 16, NT_ = WN / 8;
    constexpr int NPAIR = NT_ / 2;
    constexpr int NTOT = (BN == 128) ? 256 : 32;
    constexpr int HEADC = WN, NH = NTOT / HEADC;
    constexpr int ABYTES = BM * LDA * 2;
    constexpr int BBYTES = BN * LDA * 2;
    constexpr int STAGE = ABYTES + BBYTES;
    constexpr int ACH = BM * BK / 8;
    constexpr int BCH = BN * BK / 8;

    extern __shared__ char sm[];
    float* s_as = (float*)(sm + 3 * STAGE);
    float* s_ad = s_as + NTOT;

    const int tid = threadIdx.x;
    const int lane = tid & 31, wid = tid >> 5;
    const int wx = wid % WX, wy = wid / WX;
    const int m0 = blockIdx.y * BM;
    const int n0 = blockIdx.x * BN;

    if (tid < NTOT) { s_as[tid] = att_s[tid]; s_ad[tid] = att_d[tid]; }

    const uint32_t smBase = smem_u32(sm);

    auto issue = [&](int kt, int buf) {
        int seg = kt >> 3;
        int koff = (kt & 7) * 32;
        int aoff = ((seg < 2) ? 0 : 256) + koff;
        int boff = ((seg == 1) ? 256 : 0) + koff;
        uint32_t aS = smBase + buf * STAGE;
        uint32_t bS = aS + ABYTES;
#pragma unroll
        for (int i = 0; i < ACH / 256; i++) {
            int idx = tid + i * 256;
            int r = idx >> 2, c4 = idx & 3;
            int row = m0 + r; if (row > M - 1) row = M - 1;
            cp_async16(aS + (r * LDA + c4 * 8) * 2,
                       Aext + (size_t)row * KA + aoff + c4 * 8);
        }
        if (BCH >= 256) {
#pragma unroll
            for (int i = 0; i < BCH / 256; i++) {
                int idx = tid + i * 256;
                int r = idx >> 2, c4 = idx & 3;
                cp_async16(bS + (r * LDA + c4 * 8) * 2,
                           Bext + (size_t)(n0 + r) * KA + boff + c4 * 8);
            }
        } else if (tid < BCH) {
            int r = tid >> 2, c4 = tid & 3;
            cp_async16(bS + (r * LDA + c4 * 8) * 2,
                       Bext + (size_t)(n0 + r) * KA + boff + c4 * 8);
        }
        CP_COMMIT;
    };

    float acc[MT_][NT_][4];
#pragma unroll
    for (int mt = 0; mt < MT_; mt++)
#pragma unroll
        for (int nt = 0; nt < NT_; nt++)
#pragma unroll
            for (int q = 0; q < 4; q++) acc[mt][nt][q] = 0.f;

    const int aRow = lane & 15;
    const int aCol = (lane & 16) >> 1;
    const int bRow = (lane & 7) + ((lane & 16) >> 1);
    const int bCol = lane & 8;

    issue(0, 0);
    issue(1, 1);
    for (int kt = 0; kt < KT; kt++) {
        if (kt + 2 < KT) { CP_WAIT1; } else { CP_WAIT0; }
        __syncthreads();                      // single barrier per kt
        if (kt + 2 < KT) issue(kt + 2, (kt + 2) % 3);
        uint32_t AbU = smBase + (kt % 3) * STAGE;
        uint32_t BbU = AbU + ABYTES;
#pragma unroll
        for (int ks = 0; ks < 2; ks++) {
            const int kq0 = ks * 16;
            uint32_t a[MT_][4];
#pragma unroll
            for (int mt = 0; mt < MT_; mt++)
                ldmatrix4(a[mt], AbU + (((wy * MROWS + mt * 16 + aRow) * LDA + kq0 + aCol) << 1));
#pragma unroll
            for (int np = 0; np < NPAIR; np++) {
                uint32_t b[4];
                ldmatrix4(b, BbU + (((wx * WN + np * 16 + bRow) * LDA + kq0 + bCol) << 1));
#pragma unroll
                for (int mt = 0; mt < MT_; mt++) {
                    mma16816(acc[mt][2 * np],     a[mt], b[0], b[1]);
                    mma16816(acc[mt][2 * np + 1], a[mt], b[2], b[3]);
                }
            }
        }
        // (no trailing sync: next iteration's top barrier orders buffer reuse)
    }

    // epilogue: store C + fused att dot products (warp covers one head)
#pragma unroll
    for (int mt = 0; mt < MT_; mt++) {
        int row = m0 + wy * MROWS + mt * 16 + (lane >> 2);
        float s0 = 0.f, d0 = 0.f, s1 = 0.f, d1 = 0.f;
#pragma unroll
        for (int nt = 0; nt < NT_; nt++) {
            int col = n0 + wx * WN + nt * 8 + (lane & 3) * 2;
            float c0 = acc[mt][nt][0], c1 = acc[mt][nt][1];
            float c2 = acc[mt][nt][2], c3 = acc[mt][nt][3];
            if (row < M)     *(float2*)&Cout[(size_t)row * NTOT + col]       = make_float2(c0, c1);
            if (row + 8 < M) *(float2*)&Cout[(size_t)(row + 8) * NTOT + col] = make_float2(c2, c3);
            s0 += c0 * s_as[col] + c1 * s_as[col + 1];
            d0 += c0 * s_ad[col] + c1 * s_ad[col + 1];
            s1 += c2 * s_as[col] + c3 * s_as[col + 1];
            d1 += c2 * s_ad[col] + c3 * s_ad[col + 1];
        }
#pragma unroll
        for (int off = 1; off <= 2; off <<= 1) {
            s0 += __shfl_xor_sync(0xffffffffu, s0, off);
            d0 += __shfl_xor_sync(0xffffffffu, d0, off);
            s1 += __shfl_xor_sync(0xffffffffu, s1, off);
            d1 += __shfl_xor_sync(0xffffffffu, d1, off);
        }
        if ((lane & 3) == 0) {
            int head = (n0 + wx * WN) / HEADC;
            if (row < M)     { out_s[row * NH + head] = s0;       out_d[row * NH + head] = d0; }
            if (row + 8 < M) { out_s[(row + 8) * NH + head] = s1; out_d[(row + 8) * NH + head] = d1; }
        }
    }
}

// ---------------- layer-1 pull: warp per dst node (+g_cur reset) --------------
__global__ void __launch_bounds__(256)
pull1(const float* __restrict__ b1, int Nn) {
    int warp = (blockIdx.x * blockDim.x + threadIdx.x) >> 5;
    int lane = threadIdx.x & 31;
    if (warp >= Nn) return;
    const int d = warp;
    const int base = g_row[d], end = g_row[d + 1];
    if (lane == 0) g_cur[d] = 0;     // restore all-zero invariant for next call

    float adl = (lane < H1) ? g_ad1[d * H1 + lane] : 0.f;
    float4 acc1 = make_float4(0.f, 0.f, 0.f, 0.f);
    float4 acc2 = make_float4(0.f, 0.f, 0.f, 0.f);
    float den = 0.f;

    int src_next = g_csr[base];
    for (int i = base; i < end; i++) {
        int src = src_next;
        if (i + 1 < end) src_next = g_csr[i + 1];
        float p = 0.f;
        if (lane < H1) {
            float e = __ldg(&g_as1[src * H1 + lane]) + adl;
            e = (e >= 0.f) ? e : 0.2f * e;
            p = __expf(e);
            den += p;
        }
        float pa = __shfl_sync(0xffffffffu, p, lane >> 4);
        float pb = __shfl_sync(0xffffffffu, p, 2 + (lane >> 4));
        const float4* h4 = (const float4*)(g_h1 + (size_t)src * D1);
        float4 v1 = __ldg(h4 + lane);
        float4 v2 = __ldg(h4 + lane + 32);
        acc1.x += pa * v1.x; acc1.y += pa * v1.y; acc1.z += pa * v1.z; acc1.w += pa * v1.w;
        acc2.x += pb * v2.x; acc2.y += pb * v2.y; acc2.z += pb * v2.z; acc2.w += pb * v2.w;
    }

    float dena = __shfl_sync(0xffffffffu, den, lane >> 4);
    float denb = __shfl_sync(0xffffffffu, den, 2 + (lane >> 4));
    float inva = 1.f / dena, invb = 1.f / denb;

    size_t abase = (size_t)d * KA;
    int c1 = 4 * lane, c2 = 128 + 4 * lane;
    float v[8];
    v[0] = acc1.x * inva + __ldg(&b1[c1]);
    v[1] = acc1.y * inva + __ldg(&b1[c1 + 1]);
    v[2] = acc1.z * inva + __ldg(&b1[c1 + 2]);
    v[3] = acc1.w * inva + __ldg(&b1[c1 + 3]);
    v[4] = acc2.x * invb + __ldg(&b1[c2]);
    v[5] = acc2.y * invb + __ldg(&b1[c2 + 1]);
    v[6] = acc2.z * invb + __ldg(&b1[c2 + 2]);
    v[7] = acc2.w * invb + __ldg(&b1[c2 + 3]);
#pragma unroll
    for (int q = 0; q < 8; q++) v[q] = (v[q] > 0.f) ? v[q] : (__expf(v[q]) - 1.f);

    *(uint2*)&g_aext[abase + c1]       = make_uint2(pack_bf16x2(v[0], v[1]),    pack_bf16x2(v[2], v[3]));
    *(uint2*)&g_aext[abase + c2]       = make_uint2(pack_bf16x2(v[4], v[5]),    pack_bf16x2(v[6], v[7]));
    *(uint2*)&g_aext[abase + 256 + c1] = make_uint2(pack_bf16x2_lo(v[0], v[1]), pack_bf16x2_lo(v[2], v[3]));
    *(uint2*)&g_aext[abase + 256 + c2] = make_uint2(pack_bf16x2_lo(v[4], v[5]), pack_bf16x2_lo(v[6], v[7]));
}

// ---------------- layer-2 pull: warp per dst node, writes final output --------
__global__ void __launch_bounds__(256)
pull2(const float* __restrict__ b2, float* __restrict__ out, int Nn) {
    int warp = (blockIdx.x * blockDim.x + threadIdx.x) >> 5;
    int lane = threadIdx.x & 31;
    if (warp >= Nn) return;
    const int d = warp;
    const int base = g_row[d], end = g_row[d + 1];

    float ad = g_ad2[d];
    float acc = 0.f, den = 0.f;

    int src_next = g_csr[base];
    for (int i = base; i < end; i++) {
        int src = src_next;
        if (i + 1 < end) src_next = g_csr[i + 1];
        float p = 0.f;
        if (lane == 0) {
            float e = __ldg(&g_as2[src]) + ad;
            e = (e >= 0.f) ? e : 0.2f * e;
            p = __expf(e);
        }
        p = __shfl_sync(0xffffffffu, p, 0);
        den += p;
        acc += p * __ldg(&g_h2[(size_t)src * C2 + lane]);
    }
    out[(size_t)d * C2 + lane] = acc / den + __ldg(&b2[lane]);
}

// ---------------- host orchestration ------------------------------------------
extern "C" void kernel_launch(void* const* d_in, const int* in_sizes, int n_in,
                              void* d_out, int out_size) {
    const float* x     = (const float*)d_in[0];
    const int*   ei    = (const int*)  d_in[1];
    const float* W1    = (const float*)d_in[2];
    const float* asrc1 = (const float*)d_in[3];
    const float* adst1 = (const float*)d_in[4];
    const float* b1    = (const float*)d_in[5];
    const float* W2    = (const float*)d_in[6];
    const float* asrc2 = (const float*)d_in[7];
    const float* adst2 = (const float*)d_in[8];
    const float* b2    = (const float*)d_in[9];
    float* out = (float*)d_out;

    const int Nn = in_sizes[0] / D1;
    const int E  = in_sizes[1] / 2;
    const int Etot = E + Nn;
    const int MT = (Nn + 127) / 128;

    __nv_bfloat16 *p_aext, *p_w1, *p_w2;
    float *p_h1, *p_h2, *p_as1, *p_ad1, *p_as2, *p_ad2;
    cudaGetSymbolAddress((void**)&p_aext, g_aext);
    cudaGetSymbolAddress((void**)&p_w1,   g_wext1);
    cudaGetSymbolAddress((void**)&p_w2,   g_wext2);
    cudaGetSymbolAddress((void**)&p_h1,   g_h1);
    cudaGetSymbolAddress((void**)&p_h2,   g_h2);
    cudaGetSymbolAddress((void**)&p_as1,  g_as1);
    cudaGetSymbolAddress((void**)&p_ad1,  g_ad1);
    cudaGetSymbolAddress((void**)&p_as2,  g_as2);
    cudaGetSymbolAddress((void**)&p_ad2,  g_ad2);

    constexpr int SM1 = 3 * (128 * 40 * 2 + 128 * 40 * 2) + 2 * 256 * 4;
    constexpr int SM2 = 3 * (128 * 40 * 2 + 32 * 40 * 2)  + 2 * 32 * 4;
    cudaFuncSetAttribute(gemm_mma<128>, cudaFuncAttributeMaxDynamicSharedMemorySize, SM1);
    cudaFuncSetAttribute(gemm_mma<32>,  cudaFuncAttributeMaxDynamicSharedMemorySize, SM2);

    // fork: CSR build (count->scan->scatter) runs concurrently with prep+gemm1
    cudaStream_t s2;
    cudaStreamCreateWithFlags(&s2, cudaStreamNonBlocking);
    cudaEvent_t evFork, evJoin;
    cudaEventCreateWithFlags(&evFork, cudaEventDisableTiming);
    cudaEventCreateWithFlags(&evJoin, cudaEventDisableTiming);

    cudaEventRecord(evFork, 0);
    cudaStreamWaitEvent(s2, evFork, 0);
    csr_count  <<<(E + 255) / 256, 256, 0, s2>>>(ei, E);
    csr_scan   <<<1, 1024, 0, s2>>>(Nn);
    csr_scatter<<<(Etot + 255) / 256, 256, 0, s2>>>(ei, E, Nn);
    cudaEventRecord(evJoin, s2);

    const int prep_items = D1 * D1 + D1 * C2 + (Nn * D1) / 4;
    prep_wa<<<(prep_items + 255) / 256, 256>>>(x, W1, W2, Nn);
    gemm_mma<128><<<dim3(2, MT), 256, SM1>>>(p_aext, p_w1, p_h1, asrc1, adst1, p_as1, p_ad1, Nn);

    cudaStreamWaitEvent(0, evJoin, 0);   // join CSR before pull1

    pull1<<<(Nn + 7) / 8, 256>>>(b1, Nn);
    gemm_mma<32><<<dim3(1, MT), 256, SM2>>>(p_aext, p_w2, p_h2, asrc2, adst2, p_as2, p_ad2, Nn);
    pull2<<<(Nn + 7) / 8, 256>>>(b2, out, Nn);

    cudaEventDestroy(evFork);
    cudaEventDestroy(evJoin);
    cudaStreamDestroy(s2);
}

// round 10
// speedup vs baseline: 3.1572x; 1.0727x over previous
#include <cuda_runtime.h>
#include <cuda_bf16.h>
#include <cuda_fp16.h>
#include <cstdint>

#define MAXN 50000
#define MAXE 900080
#define D1   256
#define H1   4
#define C2   32
#define KEXT 768          // logical K (3 segments of 256)
#define KA   512          // stored K ([hi|lo])

// ---------------- scratch (device globals) -----------------------------------
__device__ __half g_h1h[MAXN * D1];            // layer-1 features, fp16
__device__ float g_as1[MAXN * H1];
__device__ float g_ad1[MAXN * H1];
__device__ float g_h2 [MAXN * C2];
__device__ float g_as2[MAXN];
__device__ float g_ad2[MAXN];
__device__ __nv_bfloat16 g_aext [MAXN * KA];   // [hi | lo]
__device__ __nv_bfloat16 g_wext1[D1 * KA];
__device__ __nv_bfloat16 g_wext2[C2 * KA];
__device__ int g_row[MAXN + 1];
__device__ int g_cur[MAXN];    // INVARIANT: all-zero between kernel_launch calls
__device__ int g_csr[MAXE];

// ---------------- helpers -----------------------------------------------------
__device__ __forceinline__ uint32_t smem_u32(const void* p) {
    uint32_t a;
    asm("{ .reg .u64 t; cvta.to.shared.u64 t, %1; cvt.u32.u64 %0, t; }" : "=r"(a) : "l"(p));
    return a;
}
__device__ __forceinline__ void cp_async16(uint32_t saddr, const void* gptr) {
    asm volatile("cp.async.cg.shared.global [%0], [%1], 16;"
        :: "r"(saddr), "l"(__cvta_generic_to_global(gptr)) : "memory");
}
#define CP_COMMIT asm volatile("cp.async.commit_group;" ::: "memory")
#define CP_WAIT0  asm volatile("cp.async.wait_group 0;" ::: "memory")
#define CP_WAIT1  asm volatile("cp.async.wait_group 1;" ::: "memory")

__device__ __forceinline__ void mma16816(float* c, const uint32_t* a, uint32_t b0, uint32_t b1) {
    asm volatile("mma.sync.aligned.m16n8k16.row.col.f32.bf16.bf16.f32 "
        "{%0,%1,%2,%3}, {%4,%5,%6,%7}, {%8,%9}, {%0,%1,%2,%3};"
        : "+f"(c[0]), "+f"(c[1]), "+f"(c[2]), "+f"(c[3])
        : "r"(a[0]), "r"(a[1]), "r"(a[2]), "r"(a[3]), "r"(b0), "r"(b1));
}
__device__ __forceinline__ void ldmatrix4(uint32_t* r, uint32_t addr) {
    asm volatile("ldmatrix.sync.aligned.m8n8.x4.shared.b16 {%0,%1,%2,%3}, [%4];"
        : "=r"(r[0]), "=r"(r[1]), "=r"(r[2]), "=r"(r[3]) : "r"(addr));
}
__device__ __forceinline__ uint32_t pack_bf16x2(float a, float b) {
    __nv_bfloat16 ha = __float2bfloat16_rn(a), hb = __float2bfloat16_rn(b);
    return (uint32_t)__bfloat16_as_ushort(ha) | ((uint32_t)__bfloat16_as_ushort(hb) << 16);
}
__device__ __forceinline__ uint32_t pack_bf16x2_lo(float a, float b) {
    __nv_bfloat16 ha = __float2bfloat16_rn(a), hb = __float2bfloat16_rn(b);
    return pack_bf16x2(a - __bfloat162float(ha), b - __bfloat162float(hb));
}
__device__ __forceinline__ uint32_t pack_h2(float a, float b) {
    __half2 h = __floats2half2_rn(a, b);
    return *(uint32_t*)&h;
}
__device__ __forceinline__ float2 unpack_h2(uint32_t u) {
    return __half22float2(*(__half2*)&u);
}

// ---------------- prep: W-ext + A-ext (vectorized) ----------------------------
__global__ void prep_wa(const float* __restrict__ x, const float* __restrict__ W1,
                        const float* __restrict__ W2, int Nn) {
    int idx = blockIdx.x * blockDim.x + threadIdx.x;
    if (idx < D1 * D1) {
        int k = idx >> 8, n = idx & 255;
        float w = W1[k * D1 + n];
        __nv_bfloat16 h = __float2bfloat16_rn(w);
        g_wext1[(size_t)n * KA + k]       = h;
        g_wext1[(size_t)n * KA + 256 + k] = __float2bfloat16_rn(w - __bfloat162float(h));
        return;
    }
    idx -= D1 * D1;
    if (idx < D1 * C2) {
        int k = idx >> 5, n = idx & 31;
        float w = W2[k * C2 + n];
        __nv_bfloat16 h = __float2bfloat16_rn(w);
        g_wext2[(size_t)n * KA + k]       = h;
        g_wext2[(size_t)n * KA + 256 + k] = __float2bfloat16_rn(w - __bfloat162float(h));
        return;
    }
    idx -= D1 * C2;
    if (idx < (Nn * D1) / 4) {
        int row = idx / (D1 / 4), c4 = idx % (D1 / 4);
        float4 v = __ldg((const float4*)(x + (size_t)row * D1) + c4);
        size_t base = (size_t)row * KA + 4 * c4;
        *(uint2*)&g_aext[base]       = make_uint2(pack_bf16x2(v.x, v.y),    pack_bf16x2(v.z, v.w));
        *(uint2*)&g_aext[base + 256] = make_uint2(pack_bf16x2_lo(v.x, v.y), pack_bf16x2_lo(v.z, v.w));
    }
}

// ---------------- CSR build (runs on forked stream) ---------------------------
__global__ void csr_count(const int* __restrict__ ei, int E) {
    int i = blockIdx.x * blockDim.x + threadIdx.x;
    if (i < E) atomicAdd(&g_cur[ei[E + i]], 1);
}
__global__ void csr_scan(int Nn) {
    __shared__ int s[1024];
    const int t = threadIdx.x;
    const int chunk = (Nn + 1023) / 1024;
    const int beg = t * chunk;
    const int end = (beg + chunk < Nn) ? beg + chunk : Nn;
    int sum = 0;
    for (int i = beg; i < end; i++) sum += g_cur[i] + 1;   // +1 self loop
    s[t] = sum;
    __syncthreads();
    int run_in = sum;
    for (int d = 1; d < 1024; d <<= 1) {
        int v = (t >= d) ? s[t - d] : 0;
        __syncthreads();
        s[t] += v;
        __syncthreads();
    }
    int run = s[t] - run_in;
    for (int i = beg; i < end; i++) {
        int c = g_cur[i] + 1;
        g_row[i] = run;
        g_cur[i] = run;
        run += c;
    }
    if (end == Nn && beg <= Nn) g_row[Nn] = run;
}
__global__ void csr_scatter(const int* __restrict__ ei, int E, int Nn) {
    int i = blockIdx.x * blockDim.x + threadIdx.x;
    int Etot = E + Nn;
    if (i >= Etot) return;
    int src, dst;
    if (i < E) { src = ei[i]; dst = ei[E + i]; }
    else       { src = dst = i - E; }
    int pos = atomicAdd(&g_cur[dst], 1);
    g_csr[pos] = src;
}

// ---------------- HMMA GEMM: ldmatrix frags, BK=32, 3-stage -------------------
// BN==128 (layer 1): C stored fp16 into g_h1h. BN==32 (layer 2): C fp32.
template<int BN>
__global__ void __launch_bounds__(256, 2)
gemm_mma(const __nv_bfloat16* __restrict__ Aext,
         const __nv_bfloat16* __restrict__ Bext,
         void* __restrict__ CoutV,
         const float* __restrict__ att_s, const float* __restrict__ att_d,
         float* __restrict__ out_s, float* __restrict__ out_d, int M)
{
    constexpr int BM = 128, BK = 32, KT = KEXT / BK;   // 24 k-tiles
    constexpr int LDA = 40;
    constexpr int WN = (BN == 128) ? 64 : 32;
    constexpr int WX = BN / WN, WY = 8 / WX;
    constexpr int MROWS = BM / WY, MT_ = MROWS / 16, NT_ = WN / 8;
    constexpr int NPAIR = NT_ / 2;
    constexpr int NTOT = (BN == 128) ? 256 : 32;
    constexpr int HEADC = WN, NH = NTOT / HEADC;
    constexpr int ABYTES = BM * LDA * 2;
    constexpr int BBYTES = BN * LDA * 2;
    constexpr int STAGE = ABYTES + BBYTES;
    constexpr int ACH = BM * BK / 8;
    constexpr int BCH = BN * BK / 8;

    extern __shared__ char sm[];
    float* s_as = (float*)(sm + 3 * STAGE);
    float* s_ad = s_as + NTOT;

    const int tid = threadIdx.x;
    const int lane = tid & 31, wid = tid >> 5;
    const int wx = wid % WX, wy = wid / WX;
    const int m0 = blockIdx.y * BM;
    const int n0 = blockIdx.x * BN;

    if (tid < NTOT) { s_as[tid] = att_s[tid]; s_ad[tid] = att_d[tid]; }

    const uint32_t smBase = smem_u32(sm);

    auto issue = [&](int kt, int buf) {
        int seg = kt >> 3;
        int koff = (kt & 7) * 32;
        int aoff = ((seg < 2) ? 0 : 256) + koff;
        int boff = ((seg == 1) ? 256 : 0) + koff;
        uint32_t aS = smBase + buf * STAGE;
        uint32_t bS = aS + ABYTES;
#pragma unroll
        for (int i = 0; i < ACH / 256; i++) {
            int idx = tid + i * 256;
            int r = idx >> 2, c4 = idx & 3;
            int row = m0 + r; if (row > M - 1) row = M - 1;
            cp_async16(aS + (r * LDA + c4 * 8) * 2,
                       Aext + (size_t)row * KA + aoff + c4 * 8);
        }
        if (BCH >= 256) {
#pragma unroll
            for (int i = 0; i < BCH / 256; i++) {
                int idx = tid + i * 256;
                int r = idx >> 2, c4 = idx & 3;
                cp_async16(bS + (r * LDA + c4 * 8) * 2,
                           Bext + (size_t)(n0 + r) * KA + boff + c4 * 8);
            }
        } else if (tid < BCH) {
            int r = tid >> 2, c4 = tid & 3;
            cp_async16(bS + (r * LDA + c4 * 8) * 2,
                       Bext + (size_t)(n0 + r) * KA + boff + c4 * 8);
        }
        CP_COMMIT;
    };

    float acc[MT_][NT_][4];
#pragma unroll
    for (int mt = 0; mt < MT_; mt++)
#pragma unroll
        for (int nt = 0; nt < NT_; nt++)
#pragma unroll
            for (int q = 0; q < 4; q++) acc[mt][nt][q] = 0.f;

    const int aRow = lane & 15;
    const int aCol = (lane & 16) >> 1;
    const int bRow = (lane & 7) + ((lane & 16) >> 1);
    const int bCol = lane & 8;

    issue(0, 0);
    issue(1, 1);
    for (int kt = 0; kt < KT; kt++) {
        if (kt + 2 < KT) { CP_WAIT1; } else { CP_WAIT0; }
        __syncthreads();
        if (kt + 2 < KT) issue(kt + 2, (kt + 2) % 3);
        uint32_t AbU = smBase + (kt % 3) * STAGE;
        uint32_t BbU = AbU + ABYTES;
#pragma unroll
        for (int ks = 0; ks < 2; ks++) {
            const int kq0 = ks * 16;
            uint32_t a[MT_][4];
#pragma unroll
            for (int mt = 0; mt < MT_; mt++)
                ldmatrix4(a[mt], AbU + (((wy * MROWS + mt * 16 + aRow) * LDA + kq0 + aCol) << 1));
#pragma unroll
            for (int np = 0; np < NPAIR; np++) {
                uint32_t b[4];
                ldmatrix4(b, BbU + (((wx * WN + np * 16 + bRow) * LDA + kq0 + bCol) << 1));
#pragma unroll
                for (int mt = 0; mt < MT_; mt++) {
                    mma16816(acc[mt][2 * np],     a[mt], b[0], b[1]);
                    mma16816(acc[mt][2 * np + 1], a[mt], b[2], b[3]);
                }
            }
        }
    }

    // epilogue: store C (fp16 for layer1, fp32 for layer2) + fused att dots
#pragma unroll
    for (int mt = 0; mt < MT_; mt++) {
        int row = m0 + wy * MROWS + mt * 16 + (lane >> 2);
        float s0 = 0.f, d0 = 0.f, s1 = 0.f, d1 = 0.f;
#pragma unroll
        for (int nt = 0; nt < NT_; nt++) {
            int col = n0 + wx * WN + nt * 8 + (lane & 3) * 2;
            float c0 = acc[mt][nt][0], c1 = acc[mt][nt][1];
            float c2 = acc[mt][nt][2], c3 = acc[mt][nt][3];
            if (BN == 128) {
                __half* Ch = (__half*)CoutV;
                if (row < M)     *(uint32_t*)&Ch[(size_t)row * NTOT + col]       = pack_h2(c0, c1);
                if (row + 8 < M) *(uint32_t*)&Ch[(size_t)(row + 8) * NTOT + col] = pack_h2(c2, c3);
            } else {
                float* Cf = (float*)CoutV;
                if (row < M)     *(float2*)&Cf[(size_t)row * NTOT + col]       = make_float2(c0, c1);
                if (row + 8 < M) *(float2*)&Cf[(size_t)(row + 8) * NTOT + col] = make_float2(c2, c3);
            }
            s0 += c0 * s_as[col] + c1 * s_as[col + 1];
            d0 += c0 * s_ad[col] + c1 * s_ad[col + 1];
            s1 += c2 * s_as[col] + c3 * s_as[col + 1];
            d1 += c2 * s_ad[col] + c3 * s_ad[col + 1];
        }
#pragma unroll
        for (int off = 1; off <= 2; off <<= 1) {
            s0 += __shfl_xor_sync(0xffffffffu, s0, off);
            d0 += __shfl_xor_sync(0xffffffffu, d0, off);
            s1 += __shfl_xor_sync(0xffffffffu, s1, off);
            d1 += __shfl_xor_sync(0xffffffffu, d1, off);
        }
        if ((lane & 3) == 0) {
            int head = (n0 + wx * WN) / HEADC;
            if (row < M)     { out_s[row * NH + head] = s0;       out_d[row * NH + head] = d0; }
            if (row + 8 < M) { out_s[(row + 8) * NH + head] = s1; out_d[(row + 8) * NH + head] = d1; }
        }
    }
}

// ---------------- layer-1 pull: warp per dst node, fp16 h1 --------------------
// lane owns features 8*lane..8*lane+7 (all in head lane>>3): ONE uint4 per edge.
__global__ void __launch_bounds__(256)
pull1(const float* __restrict__ b1, int Nn) {
    int warp = (blockIdx.x * blockDim.x + threadIdx.x) >> 5;
    int lane = threadIdx.x & 31;
    if (warp >= Nn) return;
    const int d = warp;
    const int base = g_row[d], end = g_row[d + 1];
    if (lane == 0) g_cur[d] = 0;     // restore all-zero invariant

    const int h = lane >> 3;         // head of my 8 features
    float adl = (lane < H1) ? g_ad1[d * H1 + lane] : 0.f;
    float acc[8] = {0.f, 0.f, 0.f, 0.f, 0.f, 0.f, 0.f, 0.f};
    float den = 0.f;

    int src_next = g_csr[base];
    for (int i = base; i < end; i++) {
        int src = src_next;
        if (i + 1 < end) src_next = g_csr[i + 1];
        float p = 0.f;
        if (lane < H1) {
            float e = __ldg(&g_as1[src * H1 + lane]) + adl;
            e = (e >= 0.f) ? e : 0.2f * e;
            p = __expf(e);
            den += p;
        }
        float ph = __shfl_sync(0xffffffffu, p, h);
        uint4 hv = __ldg((const uint4*)(g_h1h + (size_t)src * D1) + lane);
        float2 f0 = unpack_h2(hv.x), f1 = unpack_h2(hv.y);
        float2 f2 = unpack_h2(hv.z), f3 = unpack_h2(hv.w);
        acc[0] += ph * f0.x; acc[1] += ph * f0.y;
        acc[2] += ph * f1.x; acc[3] += ph * f1.y;
        acc[4] += ph * f2.x; acc[5] += ph * f2.y;
        acc[6] += ph * f3.x; acc[7] += ph * f3.y;
    }

    float inv = 1.f / __shfl_sync(0xffffffffu, den, h);

    const int c = 8 * lane;
    float v[8];
#pragma unroll
    for (int q = 0; q < 8; q++) {
        v[q] = acc[q] * inv + __ldg(&b1[c + q]);
        v[q] = (v[q] > 0.f) ? v[q] : (__expf(v[q]) - 1.f);
    }

    size_t abase = (size_t)d * KA;
    *(uint4*)&g_aext[abase + c] = make_uint4(
        pack_bf16x2(v[0], v[1]), pack_bf16x2(v[2], v[3]),
        pack_bf16x2(v[4], v[5]), pack_bf16x2(v[6], v[7]));
    *(uint4*)&g_aext[abase + 256 + c] = make_uint4(
        pack_bf16x2_lo(v[0], v[1]), pack_bf16x2_lo(v[2], v[3]),
        pack_bf16x2_lo(v[4], v[5]), pack_bf16x2_lo(v[6], v[7]));
}

// ---------------- layer-2 pull: warp per dst node, writes final output --------
__global__ void __launch_bounds__(256)
pull2(const float* __restrict__ b2, float* __restrict__ out, int Nn) {
    int warp = (blockIdx.x * blockDim.x + threadIdx.x) >> 5;
    int lane = threadIdx.x & 31;
    if (warp >= Nn) return;
    const int d = warp;
    const int base = g_row[d], end = g_row[d + 1];

    float ad = g_ad2[d];
    float acc = 0.f, den = 0.f;

    int src_next = g_csr[base];
    for (int i = base; i < end; i++) {
        int src = src_next;
        if (i + 1 < end) src_next = g_csr[i + 1];
        float p = 0.f;
        if (lane == 0) {
            float e = __ldg(&g_as2[src]) + ad;
            e = (e >= 0.f) ? e : 0.2f * e;
            p = __expf(e);
        }
        p = __shfl_sync(0xffffffffu, p, 0);
        den += p;
        acc += p * __ldg(&g_h2[(size_t)src * C2 + lane]);
    }
    out[(size_t)d * C2 + lane] = acc / den + __ldg(&b2[lane]);
}

// ---------------- host orchestration ------------------------------------------
extern "C" void kernel_launch(void* const* d_in, const int* in_sizes, int n_in,
                              void* d_out, int out_size) {
    const float* x     = (const float*)d_in[0];
    const int*   ei    = (const int*)  d_in[1];
    const float* W1    = (const float*)d_in[2];
    const float* asrc1 = (const float*)d_in[3];
    const float* adst1 = (const float*)d_in[4];
    const float* b1    = (const float*)d_in[5];
    const float* W2    = (const float*)d_in[6];
    const float* asrc2 = (const float*)d_in[7];
    const float* adst2 = (const float*)d_in[8];
    const float* b2    = (const float*)d_in[9];
    float* out = (float*)d_out;

    const int Nn = in_sizes[0] / D1;
    const int E  = in_sizes[1] / 2;
    const int Etot = E + Nn;
    const int MT = (Nn + 127) / 128;

    __nv_bfloat16 *p_aext, *p_w1, *p_w2;
    __half *p_h1h;
    float *p_h2, *p_as1, *p_ad1, *p_as2, *p_ad2;
    cudaGetSymbolAddress((void**)&p_aext, g_aext);
    cudaGetSymbolAddress((void**)&p_w1,   g_wext1);
    cudaGetSymbolAddress((void**)&p_w2,   g_wext2);
    cudaGetSymbolAddress((void**)&p_h1h,  g_h1h);
    cudaGetSymbolAddress((void**)&p_h2,   g_h2);
    cudaGetSymbolAddress((void**)&p_as1,  g_as1);
    cudaGetSymbolAddress((void**)&p_ad1,  g_ad1);
    cudaGetSymbolAddress((void**)&p_as2,  g_as2);
    cudaGetSymbolAddress((void**)&p_ad2,  g_ad2);

    constexpr int SM1 = 3 * (128 * 40 * 2 + 128 * 40 * 2) + 2 * 256 * 4;
    constexpr int SM2 = 3 * (128 * 40 * 2 + 32 * 40 * 2)  + 2 * 32 * 4;
    cudaFuncSetAttribute(gemm_mma<128>, cudaFuncAttributeMaxDynamicSharedMemorySize, SM1);
    cudaFuncSetAttribute(gemm_mma<32>,  cudaFuncAttributeMaxDynamicSharedMemorySize, SM2);

    // fork: CSR build runs concurrently with prep+gemm1
    cudaStream_t s2;
    cudaStreamCreateWithFlags(&s2, cudaStreamNonBlocking);
    cudaEvent_t evFork, evJoin;
    cudaEventCreateWithFlags(&evFork, cudaEventDisableTiming);
    cudaEventCreateWithFlags(&evJoin, cudaEventDisableTiming);

    cudaEventRecord(evFork, 0);
    cudaStreamWaitEvent(s2, evFork, 0);
    csr_count  <<<(E + 255) / 256, 256, 0, s2>>>(ei, E);
    csr_scan   <<<1, 1024, 0, s2>>>(Nn);
    csr_scatter<<<(Etot + 255) / 256, 256, 0, s2>>>(ei, E, Nn);
    cudaEventRecord(evJoin, s2);

    const int prep_items = D1 * D1 + D1 * C2 + (Nn * D1) / 4;
    prep_wa<<<(prep_items + 255) / 256, 256>>>(x, W1, W2, Nn);
    gemm_mma<128><<<dim3(2, MT), 256, SM1>>>(p_aext, p_w1, p_h1h, asrc1, adst1, p_as1, p_ad1, Nn);

    cudaStreamWaitEvent(0, evJoin, 0);   // join CSR before pull1

    pull1<<<(Nn + 7) / 8, 256>>>(b1, Nn);
    gemm_mma<32><<<dim3(1, MT), 256, SM2>>>(p_aext, p_w2, p_h2, asrc2, adst2, p_as2, p_ad2, Nn);
    pull2<<<(Nn + 7) / 8, 256>>>(b2, out, Nn);

    cudaEventDestroy(evFork);
    cudaEventDestroy(evJoin);
    cudaStreamDestroy(s2);
}

// round 11
// speedup vs baseline: 3.4877x; 1.1047x over previous
#include <cuda_runtime.h>
#include <cuda_bf16.h>
#include <cuda_fp16.h>
#include <cstdint>

#define MAXN 50000
#define MAXE 900080
#define D1   256
#define H1   4
#define C2   32
#define KA   256          // stored K (single fp16 plane)

// ---------------- scratch (device globals) -----------------------------------
__device__ __half g_h1h[MAXN * D1];            // layer-1 features, fp16
__device__ float g_as1[MAXN * H1];
__device__ float g_ad1[MAXN * H1];
__device__ float g_h2 [MAXN * C2];
__device__ float g_as2[MAXN];
__device__ float g_ad2[MAXN];
__device__ __half g_xh [MAXN * KA];            // x in fp16 (GEMM1 A)
__device__ __half g_a2h[MAXN * KA];            // layer-2 A (ELU acts, fp16)
__device__ __half g_w1h[D1 * KA];              // W1^T fp16
__device__ __half g_w2h[C2 * KA];              // W2^T fp16
__device__ int g_row[MAXN + 1];
__device__ int g_cur[MAXN];    // INVARIANT: all-zero between kernel_launch calls
__device__ int g_csr[MAXE];

// ---------------- helpers -----------------------------------------------------
__device__ __forceinline__ uint32_t smem_u32(const void* p) {
    uint32_t a;
    asm("{ .reg .u64 t; cvta.to.shared.u64 t, %1; cvt.u32.u64 %0, t; }" : "=r"(a) : "l"(p));
    return a;
}
__device__ __forceinline__ void cp_async16(uint32_t saddr, const void* gptr) {
    asm volatile("cp.async.cg.shared.global [%0], [%1], 16;"
        :: "r"(saddr), "l"(__cvta_generic_to_global(gptr)) : "memory");
}
#define CP_COMMIT asm volatile("cp.async.commit_group;" ::: "memory")
#define CP_WAIT0  asm volatile("cp.async.wait_group 0;" ::: "memory")
#define CP_WAIT1  asm volatile("cp.async.wait_group 1;" ::: "memory")

__device__ __forceinline__ void mma16816h(float* c, const uint32_t* a, uint32_t b0, uint32_t b1) {
    asm volatile("mma.sync.aligned.m16n8k16.row.col.f32.f16.f16.f32 "
        "{%0,%1,%2,%3}, {%4,%5,%6,%7}, {%8,%9}, {%0,%1,%2,%3};"
        : "+f"(c[0]), "+f"(c[1]), "+f"(c[2]), "+f"(c[3])
        : "r"(a[0]), "r"(a[1]), "r"(a[2]), "r"(a[3]), "r"(b0), "r"(b1));
}
__device__ __forceinline__ void ldmatrix4(uint32_t* r, uint32_t addr) {
    asm volatile("ldmatrix.sync.aligned.m8n8.x4.shared.b16 {%0,%1,%2,%3}, [%4];"
        : "=r"(r[0]), "=r"(r[1]), "=r"(r[2]), "=r"(r[3]) : "r"(addr));
}
__device__ __forceinline__ uint32_t pack_h2(float a, float b) {
    __half2 h = __floats2half2_rn(a, b);
    return *(uint32_t*)&h;
}
__device__ __forceinline__ float2 unpack_h2(uint32_t u) {
    return __half22float2(*(__half2*)&u);
}

// ---------------- prep: fp16 W^T + fp16 x copy --------------------------------
__global__ void prep_wa(const float* __restrict__ x, const float* __restrict__ W1,
                        const float* __restrict__ W2, int Nn) {
    int idx = blockIdx.x * blockDim.x + threadIdx.x;
    if (idx < D1 * D1) {
        int k = idx >> 8, n = idx & 255;
        g_w1h[(size_t)n * KA + k] = __float2half_rn(W1[k * D1 + n]);
        return;
    }
    idx -= D1 * D1;
    if (idx < D1 * C2) {
        int k = idx >> 5, n = idx & 31;
        g_w2h[(size_t)n * KA + k] = __float2half_rn(W2[k * C2 + n]);
        return;
    }
    idx -= D1 * C2;
    if (idx < (Nn * D1) / 4) {
        int row = idx / (D1 / 4), c4 = idx % (D1 / 4);
        float4 v = __ldg((const float4*)(x + (size_t)row * D1) + c4);
        *(uint2*)&g_xh[(size_t)row * KA + 4 * c4] =
            make_uint2(pack_h2(v.x, v.y), pack_h2(v.z, v.w));
    }
}

// ---------------- CSR build (runs on forked stream) ---------------------------
__global__ void csr_count(const int* __restrict__ ei, int E) {
    int i = blockIdx.x * blockDim.x + threadIdx.x;
    if (i < E) atomicAdd(&g_cur[ei[E + i]], 1);
}
__global__ void csr_scan(int Nn) {
    __shared__ int s[1024];
    const int t = threadIdx.x;
    const int chunk = (Nn + 1023) / 1024;
    const int beg = t * chunk;
    const int end = (beg + chunk < Nn) ? beg + chunk : Nn;
    int sum = 0;
    for (int i = beg; i < end; i++) sum += g_cur[i] + 1;   // +1 self loop
    s[t] = sum;
    __syncthreads();
    int run_in = sum;
    for (int d = 1; d < 1024; d <<= 1) {
        int v = (t >= d) ? s[t - d] : 0;
        __syncthreads();
        s[t] += v;
        __syncthreads();
    }
    int run = s[t] - run_in;
    for (int i = beg; i < end; i++) {
        int c = g_cur[i] + 1;
        g_row[i] = run;
        g_cur[i] = run;
        run += c;
    }
    if (end == Nn && beg <= Nn) g_row[Nn] = run;
}
__global__ void csr_scatter(const int* __restrict__ ei, int E, int Nn) {
    int i = blockIdx.x * blockDim.x + threadIdx.x;
    int Etot = E + Nn;
    if (i >= Etot) return;
    int src, dst;
    if (i < E) { src = ei[i]; dst = ei[E + i]; }
    else       { src = dst = i - E; }
    int pos = atomicAdd(&g_cur[dst], 1);
    g_csr[pos] = src;
}

// ---------------- fp16 HMMA GEMM: K=256, ldmatrix, BK=32, 3-stage -------------
// BN==128 (layer 1): C stored fp16 into g_h1h. BN==32 (layer 2): C fp32.
template<int BN>
__global__ void __launch_bounds__(256, 2)
gemm_mma(const __half* __restrict__ Ah,
         const __half* __restrict__ Bh,
         void* __restrict__ CoutV,
         const float* __restrict__ att_s, const float* __restrict__ att_d,
         float* __restrict__ out_s, float* __restrict__ out_d, int M)
{
    constexpr int BM = 128, BK = 32, KT = KA / BK;   // 8 k-tiles
    constexpr int LDA = 40;
    constexpr int WN = (BN == 128) ? 64 : 32;
    constexpr int WX = BN / WN, WY = 8 / WX;
    constexpr int MROWS = BM / WY, MT_ = MROWS / 16, NT_ = WN / 8;
    constexpr int NPAIR = NT_ / 2;
    constexpr int NTOT = (BN == 128) ? 256 : 32;
    constexpr int HEADC = WN, NH = NTOT / HEADC;
    constexpr int ABYTES = BM * LDA * 2;
    constexpr int BBYTES = BN * LDA * 2;
    constexpr int STAGE = ABYTES + BBYTES;
    constexpr int ACH = BM * BK / 8;
    constexpr int BCH = BN * BK / 8;

    extern __shared__ char sm[];
    float* s_as = (float*)(sm + 3 * STAGE);
    float* s_ad = s_as + NTOT;

    const int tid = threadIdx.x;
    const int lane = tid & 31, wid = tid >> 5;
    const int wx = wid % WX, wy = wid / WX;
    const int m0 = blockIdx.y * BM;
    const int n0 = blockIdx.x * BN;

    if (tid < NTOT) { s_as[tid] = att_s[tid]; s_ad[tid] = att_d[tid]; }

    const uint32_t smBase = smem_u32(sm);

    auto issue = [&](int kt, int buf) {
        int koff = kt * 32;
        uint32_t aS = smBase + buf * STAGE;
        uint32_t bS = aS + ABYTES;
#pragma unroll
        for (int i = 0; i < ACH / 256; i++) {
            int idx = tid + i * 256;
            int r = idx >> 2, c4 = idx & 3;
            int row = m0 + r; if (row > M - 1) row = M - 1;
            cp_async16(aS + (r * LDA + c4 * 8) * 2,
                       Ah + (size_t)row * KA + koff + c4 * 8);
        }
        if (BCH >= 256) {
#pragma unroll
            for (int i = 0; i < BCH / 256; i++) {
                int idx = tid + i * 256;
                int r = idx >> 2, c4 = idx & 3;
                cp_async16(bS + (r * LDA + c4 * 8) * 2,
                           Bh + (size_t)(n0 + r) * KA + koff + c4 * 8);
            }
        } else if (tid < BCH) {
            int r = tid >> 2, c4 = tid & 3;
            cp_async16(bS + (r * LDA + c4 * 8) * 2,
                       Bh + (size_t)(n0 + r) * KA + koff + c4 * 8);
        }
        CP_COMMIT;
    };

    float acc[MT_][NT_][4];
#pragma unroll
    for (int mt = 0; mt < MT_; mt++)
#pragma unroll
        for (int nt = 0; nt < NT_; nt++)
#pragma unroll
            for (int q = 0; q < 4; q++) acc[mt][nt][q] = 0.f;

    const int aRow = lane & 15;
    const int aCol = (lane & 16) >> 1;
    const int bRow = (lane & 7) + ((lane & 16) >> 1);
    const int bCol = lane & 8;

    issue(0, 0);
    issue(1, 1);
    for (int kt = 0; kt < KT; kt++) {
        if (kt + 2 < KT) { CP_WAIT1; } else { CP_WAIT0; }
        __syncthreads();
        if (kt + 2 < KT) issue(kt + 2, (kt + 2) % 3);
        uint32_t AbU = smBase + (kt % 3) * STAGE;
        uint32_t BbU = AbU + ABYTES;
#pragma unroll
        for (int ks = 0; ks < 2; ks++) {
            const int kq0 = ks * 16;
            uint32_t a[MT_][4];
#pragma unroll
            for (int mt = 0; mt < MT_; mt++)
                ldmatrix4(a[mt], AbU + (((wy * MROWS + mt * 16 + aRow) * LDA + kq0 + aCol) << 1));
#pragma unroll
            for (int np = 0; np < NPAIR; np++) {
                uint32_t b[4];
                ldmatrix4(b, BbU + (((wx * WN + np * 16 + bRow) * LDA + kq0 + bCol) << 1));
#pragma unroll
                for (int mt = 0; mt < MT_; mt++) {
                    mma16816h(acc[mt][2 * np],     a[mt], b[0], b[1]);
                    mma16816h(acc[mt][2 * np + 1], a[mt], b[2], b[3]);
                }
            }
        }
    }

    // epilogue: store C (fp16 for layer1, fp32 for layer2) + fused att dots
#pragma unroll
    for (int mt = 0; mt < MT_; mt++) {
        int row = m0 + wy * MROWS + mt * 16 + (lane >> 2);
        float s0 = 0.f, d0 = 0.f, s1 = 0.f, d1 = 0.f;
#pragma unroll
        for (int nt = 0; nt < NT_; nt++) {
            int col = n0 + wx * WN + nt * 8 + (lane & 3) * 2;
            float c0 = acc[mt][nt][0], c1 = acc[mt][nt][1];
            float c2 = acc[mt][nt][2], c3 = acc[mt][nt][3];
            if (BN == 128) {
                __half* Ch = (__half*)CoutV;
                if (row < M)     *(uint32_t*)&Ch[(size_t)row * NTOT + col]       = pack_h2(c0, c1);
                if (row + 8 < M) *(uint32_t*)&Ch[(size_t)(row + 8) * NTOT + col] = pack_h2(c2, c3);
            } else {
                float* Cf = (float*)CoutV;
                if (row < M)     *(float2*)&Cf[(size_t)row * NTOT + col]       = make_float2(c0, c1);
                if (row + 8 < M) *(float2*)&Cf[(size_t)(row + 8) * NTOT + col] = make_float2(c2, c3);
            }
            s0 += c0 * s_as[col] + c1 * s_as[col + 1];
            d0 += c0 * s_ad[col] + c1 * s_ad[col + 1];
            s1 += c2 * s_as[col] + c3 * s_as[col + 1];
            d1 += c2 * s_ad[col] + c3 * s_ad[col + 1];
        }
#pragma unroll
        for (int off = 1; off <= 2; off <<= 1) {
            s0 += __shfl_xor_sync(0xffffffffu, s0, off);
            d0 += __shfl_xor_sync(0xffffffffu, d0, off);
            s1 += __shfl_xor_sync(0xffffffffu, s1, off);
            d1 += __shfl_xor_sync(0xffffffffu, d1, off);
        }
        if ((lane & 3) == 0) {
            int head = (n0 + wx * WN) / HEADC;
            if (row < M)     { out_s[row * NH + head] = s0;       out_d[row * NH + head] = d0; }
            if (row + 8 < M) { out_s[(row + 8) * NH + head] = s1; out_d[(row + 8) * NH + head] = d1; }
        }
    }
}

// ---------------- layer-1 pull: warp per dst node, fp16 h1 --------------------
// lane owns features 8*lane..8*lane+7 (all in head lane>>3): ONE uint4 per edge.
__global__ void __launch_bounds__(256)
pull1(const float* __restrict__ b1, int Nn) {
    int warp = (blockIdx.x * blockDim.x + threadIdx.x) >> 5;
    int lane = threadIdx.x & 31;
    if (warp >= Nn) return;
    const int d = warp;
    const int base = g_row[d], end = g_row[d + 1];
    if (lane == 0) g_cur[d] = 0;     // restore all-zero invariant

    const int h = lane >> 3;         // head of my 8 features
    float adl = (lane < H1) ? g_ad1[d * H1 + lane] : 0.f;
    float acc[8] = {0.f, 0.f, 0.f, 0.f, 0.f, 0.f, 0.f, 0.f};
    float den = 0.f;

    int src_next = g_csr[base];
    for (int i = base; i < end; i++) {
        int src = src_next;
        if (i + 1 < end) src_next = g_csr[i + 1];
        float p = 0.f;
        if (lane < H1) {
            float e = __ldg(&g_as1[src * H1 + lane]) + adl;
            e = (e >= 0.f) ? e : 0.2f * e;
            p = __expf(e);
            den += p;
        }
        float ph = __shfl_sync(0xffffffffu, p, h);
        uint4 hv = __ldg((const uint4*)(g_h1h + (size_t)src * D1) + lane);
        float2 f0 = unpack_h2(hv.x), f1 = unpack_h2(hv.y);
        float2 f2 = unpack_h2(hv.z), f3 = unpack_h2(hv.w);
        acc[0] += ph * f0.x; acc[1] += ph * f0.y;
        acc[2] += ph * f1.x; acc[3] += ph * f1.y;
        acc[4] += ph * f2.x; acc[5] += ph * f2.y;
        acc[6] += ph * f3.x; acc[7] += ph * f3.y;
    }

    float inv = 1.f / __shfl_sync(0xffffffffu, den, h);

    const int c = 8 * lane;
    float v[8];
#pragma unroll
    for (int q = 0; q < 8; q++) {
        v[q] = acc[q] * inv + __ldg(&b1[c + q]);
        v[q] = (v[q] > 0.f) ? v[q] : (__expf(v[q]) - 1.f);
    }

    *(uint4*)&g_a2h[(size_t)d * KA + c] = make_uint4(
        pack_h2(v[0], v[1]), pack_h2(v[2], v[3]),
        pack_h2(v[4], v[5]), pack_h2(v[6], v[7]));
}

// ---------------- layer-2 pull: warp per dst node, writes final output --------
__global__ void __launch_bounds__(256)
pull2(const float* __restrict__ b2, float* __restrict__ out, int Nn) {
    int warp = (blockIdx.x * blockDim.x + threadIdx.x) >> 5;
    int lane = threadIdx.x & 31;
    if (warp >= Nn) return;
    const int d = warp;
    const int base = g_row[d], end = g_row[d + 1];

    float ad = g_ad2[d];
    float acc = 0.f, den = 0.f;

    int src_next = g_csr[base];
    for (int i = base; i < end; i++) {
        int src = src_next;
        if (i + 1 < end) src_next = g_csr[i + 1];
        float p = 0.f;
        if (lane == 0) {
            float e = __ldg(&g_as2[src]) + ad;
            e = (e >= 0.f) ? e : 0.2f * e;
            p = __expf(e);
        }
        p = __shfl_sync(0xffffffffu, p, 0);
        den += p;
        acc += p * __ldg(&g_h2[(size_t)src * C2 + lane]);
    }
    out[(size_t)d * C2 + lane] = acc / den + __ldg(&b2[lane]);
}

// ---------------- host orchestration ------------------------------------------
extern "C" void kernel_launch(void* const* d_in, const int* in_sizes, int n_in,
                              void* d_out, int out_size) {
    const float* x     = (const float*)d_in[0];
    const int*   ei    = (const int*)  d_in[1];
    const float* W1    = (const float*)d_in[2];
    const float* asrc1 = (const float*)d_in[3];
    const float* adst1 = (const float*)d_in[4];
    const float* b1    = (const float*)d_in[5];
    const float* W2    = (const float*)d_in[6];
    const float* asrc2 = (const float*)d_in[7];
    const float* adst2 = (const float*)d_in[8];
    const float* b2    = (const float*)d_in[9];
    float* out = (float*)d_out;

    const int Nn = in_sizes[0] / D1;
    const int E  = in_sizes[1] / 2;
    const int Etot = E + Nn;
    const int MT = (Nn + 127) / 128;

    __half *p_xh, *p_a2h, *p_w1h, *p_w2h, *p_h1h;
    float *p_h2, *p_as1, *p_ad1, *p_as2, *p_ad2;
    cudaGetSymbolAddress((void**)&p_xh,   g_xh);
    cudaGetSymbolAddress((void**)&p_a2h,  g_a2h);
    cudaGetSymbolAddress((void**)&p_w1h,  g_w1h);
    cudaGetSymbolAddress((void**)&p_w2h,  g_w2h);
    cudaGetSymbolAddress((void**)&p_h1h,  g_h1h);
    cudaGetSymbolAddress((void**)&p_h2,   g_h2);
    cudaGetSymbolAddress((void**)&p_as1,  g_as1);
    cudaGetSymbolAddress((void**)&p_ad1,  g_ad1);
    cudaGetSymbolAddress((void**)&p_as2,  g_as2);
    cudaGetSymbolAddress((void**)&p_ad2,  g_ad2);

    constexpr int SM1 = 3 * (128 * 40 * 2 + 128 * 40 * 2) + 2 * 256 * 4;
    constexpr int SM2 = 3 * (128 * 40 * 2 + 32 * 40 * 2)  + 2 * 32 * 4;
    cudaFuncSetAttribute(gemm_mma<128>, cudaFuncAttributeMaxDynamicSharedMemorySize, SM1);
    cudaFuncSetAttribute(gemm_mma<32>,  cudaFuncAttributeMaxDynamicSharedMemorySize, SM2);

    // fork: CSR build runs concurrently with prep+gemm1
    cudaStream_t s2;
    cudaStreamCreateWithFlags(&s2, cudaStreamNonBlocking);
    cudaEvent_t evFork, evJoin;
    cudaEventCreateWithFlags(&evFork, cudaEventDisableTiming);
    cudaEventCreateWithFlags(&evJoin, cudaEventDisableTiming);

    cudaEventRecord(evFork, 0);
    cudaStreamWaitEvent(s2, evFork, 0);
    csr_count  <<<(E + 255) / 256, 256, 0, s2>>>(ei, E);
    csr_scan   <<<1, 1024, 0, s2>>>(Nn);
    csr_scatter<<<(Etot + 255) / 256, 256, 0, s2>>>(ei, E, Nn);
    cudaEventRecord(evJoin, s2);

    const int prep_items = D1 * D1 + D1 * C2 + (Nn * D1) / 4;
    prep_wa<<<(prep_items + 255) / 256, 256>>>(x, W1, W2, Nn);
    gemm_mma<128><<<dim3(2, MT), 256, SM1>>>(p_xh, p_w1h, p_h1h, asrc1, adst1, p_as1, p_ad1, Nn);

    cudaStreamWaitEvent(0, evJoin, 0);   // join CSR before pull1

    pull1<<<(Nn + 7) / 8, 256>>>(b1, Nn);
    gemm_mma<32><<<dim3(1, MT), 256, SM2>>>(p_a2h, p_w2h, p_h2, asrc2, adst2, p_as2, p_ad2, Nn);
    pull2<<<(Nn + 7) / 8, 256>>>(b2, out, Nn);

    cudaEventDestroy(evFork);
    cudaEventDestroy(evJoin);
    cudaStreamDestroy(s2);
}